// round 9
// baseline (speedup 1.0000x reference)
#include <cuda_runtime.h>
#include <cuda_bf16.h>
#include <cstdint>

#define NATOMS 10000
#define NPAIRS 320000
#define FDIM 128
#define KDIM 64
#define NB 5
#define NRI 3
#define NRA 2

// bf16 padded plane: 128 bf16/row = 64 words + 4 pad = 68 words
#define PW 68
#define A_LO 4352
#define WPLANE 8704          // one plane = 128 rows * 68 words
#define MATW 17408           // matrix = hi+lo planes

// mega smem layout (word offsets)
#define MG_XM 0
#define MG_XX 8448
#define MG_AHI 16896
#define MG_ALO 21248
#define MG_B0 25600
#define MG_B1 34304
#define SM_MEGA (43008 * 4)  // 172032 B

// dual smem layout
#define DU_B0 8704
#define DU_B1 17408
#define SM_DUAL (26112 * 4)  // 104448 B -> 2 CTAs/SM

// message MMA smem
#define MPW 36
#define OFF_RBFH 9216
#define OFF_RBFL 11520
#define OFF_G 13824
#define SM_MSG ((13824 + 8448) * 4)
#define NCH (NPAIRS / 64)

// ---------------- scratch ----------------
__device__ uint32_t g_rbfh[NPAIRS * 32];
__device__ uint32_t g_rbfl[NPAIRS * 32];
__device__ uint32_t g_k2fb[5 * 9216];
__device__ float g_x [NATOMS * FDIM];
__device__ float g_xj[NATOMS * FDIM];
__device__ float g_m [NATOMS * FDIM];
__device__ float g_Ea[NATOMS];
__device__ float g_Qa[NATOMS];
__device__ float g_l2[NATOMS * 2];
__device__ float g_nh;
__device__ uint32_t g_wbf[75 * MATW];

__device__ __forceinline__ float actf(float x) {
    return fmaxf(x, 0.f) + log1pf(__expf(-fabsf(x))) - 0.69314718055994531f;
}

__device__ __forceinline__ void red_add_f4(float* p, float4 v) {
    asm volatile("red.global.add.v4.f32 [%0], {%1,%2,%3,%4};"
                 :: "l"(p), "f"(v.x), "f"(v.y), "f"(v.z), "f"(v.w) : "memory");
}

__device__ __forceinline__ uint32_t pack_hi(float a, float b) {
    __nv_bfloat16 h0 = __float2bfloat16(a), h1 = __float2bfloat16(b);
    return (uint32_t)__bfloat16_as_ushort(h0) | ((uint32_t)__bfloat16_as_ushort(h1) << 16);
}
__device__ __forceinline__ uint32_t pack_lo(float a, float b) {
    __nv_bfloat16 h0 = __float2bfloat16(a), h1 = __float2bfloat16(b);
    float r0 = a - __bfloat162float(h0), r1 = b - __bfloat162float(h1);
    __nv_bfloat16 l0 = __float2bfloat16(r0), l1 = __float2bfloat16(r1);
    return (uint32_t)__bfloat16_as_ushort(l0) | ((uint32_t)__bfloat16_as_ushort(l1) << 16);
}

__device__ __forceinline__ void mma_bf16(float c[4], const uint32_t a[4], const uint32_t b[2]) {
    asm volatile(
        "mma.sync.aligned.m16n8k16.row.col.f32.bf16.bf16.f32 "
        "{%0,%1,%2,%3}, {%4,%5,%6,%7}, {%8,%9}, {%0,%1,%2,%3};"
        : "+f"(c[0]), "+f"(c[1]), "+f"(c[2]), "+f"(c[3])
        : "r"(a[0]), "r"(a[1]), "r"(a[2]), "r"(a[3]), "r"(b[0]), "r"(b[1]));
}

#define CP_COMMIT() asm volatile("cp.async.commit_group;" ::: "memory")
#define CP_WAIT1()  asm volatile("cp.async.wait_group 1;" ::: "memory")
#define CP_WAIT0()  asm volatile("cp.async.wait_group 0;" ::: "memory")

__device__ __forceinline__ void prefetch_plane(uint32_t* sm, int boff,
                                               const uint32_t* __restrict__ gsrc, int tid) {
    uint32_t sb = (uint32_t)__cvta_generic_to_shared(sm + boff);
#pragma unroll
    for (int i = 0; i < 9; i++) {
        int v = tid + i * 256;
        if (v < 2176)
            asm volatile("cp.async.cg.shared.global [%0], [%1], 16;"
                         :: "r"(sb + v * 16), "l"(gsrc + v * 4) : "memory");
    }
}

// one plane-pass: acc += A(aoff) @ B(boff)^T, warp tile 32x32, K=128
__device__ __forceinline__ void pass_plane(const uint32_t* __restrict__ sm, int aoff, int boff,
                                           int wr0, int wc0, int lane, float acc[2][4][4]) {
    const int g = lane >> 2, tig = lane & 3;
#pragma unroll
    for (int ks = 0; ks < 8; ks++) {
        const int kw = ks * 8 + tig;
        uint32_t a[2][4];
#pragma unroll
        for (int mg = 0; mg < 2; mg++) {
            int ba = aoff + (wr0 + mg * 16 + g) * PW + kw;
            a[mg][0] = sm[ba];     a[mg][1] = sm[ba + 8 * PW];
            a[mg][2] = sm[ba + 4]; a[mg][3] = sm[ba + 8 * PW + 4];
        }
#pragma unroll
        for (int ng = 0; ng < 4; ng++) {
            int nb = boff + (wc0 + ng * 8 + g) * PW + kw;
            uint32_t bb[2] = { sm[nb], sm[nb + 4] };
#pragma unroll
            for (int mg = 0; mg < 2; mg++) mma_bf16(acc[mg][ng], a[mg], bb);
        }
    }
}

__device__ __forceinline__ void zero_acc(float acc[2][4][4]) {
#pragma unroll
    for (int a = 0; a < 2; a++)
#pragma unroll
        for (int b = 0; b < 4; b++)
#pragma unroll
            for (int c = 0; c < 4; c++) acc[a][b][c] = 0.f;
}

// 3-pass matrix with double-buffered plane prefetch of the NEXT matrix.
// invariant on entry: planes (hi,lo) of current matrix are the 2 pending cp.async groups.
__device__ __forceinline__ void do_matrix(uint32_t* sm, float acc[2][4][4],
    int ahi, int alo, int b0, int b1o,
    const uint32_t* nxh, const uint32_t* nxl, int wr0, int wc0, int lane, int tid) {
    CP_WAIT1(); __syncthreads();
    pass_plane(sm, ahi, b0, wr0, wc0, lane, acc);
    pass_plane(sm, alo, b0, wr0, wc0, lane, acc);
    __syncthreads();
    if (nxh) prefetch_plane(sm, b0, nxh, tid);
    CP_COMMIT();
    CP_WAIT1(); __syncthreads();
    pass_plane(sm, ahi, b1o, wr0, wc0, lane, acc);
    __syncthreads();
    if (nxl) prefetch_plane(sm, b1o, nxl, tid);
    CP_COMMIT();
}

// ---- A tile from gmem: fp32 -> act -> bf16 hi/lo planes at offsets 0 / A_LO ----
__device__ __forceinline__ void conv_A(const float* __restrict__ A, uint32_t* sm,
                                       int tid, int r0, int nrows) {
#pragma unroll 4
    for (int i = 0; i < 16; i++) {
        int v = tid + i * 256;
        int row = v >> 6, kp = v & 63;
        float2 av = make_float2(0.f, 0.f);
        if (r0 + row < nrows) av = *(const float2*)(A + (size_t)(r0 + row) * FDIM + kp * 2);
        av.x = actf(av.x); av.y = actf(av.y);
        sm[row * PW + kp]        = pack_hi(av.x, av.y);
        sm[A_LO + row * PW + kp] = pack_lo(av.x, av.y);
    }
}

// ---- dual: C1 = act(act(A)@W1+b1), C2 = act(act(A)@W2+b2); 2 CTAs/SM ----
__global__ void __launch_bounds__(256, 2) gemm_dual_mma(
    const float* __restrict__ A, const uint32_t* __restrict__ w1,
    const uint32_t* __restrict__ w2, const float* __restrict__ b1,
    const float* __restrict__ b2, float* __restrict__ C1, float* __restrict__ C2, int nrows) {
    extern __shared__ uint32_t sm[];
    const int tid = threadIdx.x, lane = tid & 31, wid = tid >> 5;
    const int wr0 = (wid >> 2) * 32, wc0 = (wid & 3) * 32;
    const int r0 = blockIdx.x * 64;
    const int g = lane >> 2, tig = lane & 3;

    prefetch_plane(sm, DU_B0, w1, tid); CP_COMMIT();
    prefetch_plane(sm, DU_B1, w1 + WPLANE, tid); CP_COMMIT();
    conv_A(A, sm, tid, r0, nrows);

    float acc[2][4][4];
#pragma unroll
    for (int ph = 0; ph < 2; ph++) {
        zero_acc(acc);
        do_matrix(sm, acc, 0, A_LO, DU_B0, DU_B1,
                  ph == 0 ? w2 : nullptr, ph == 0 ? w2 + WPLANE : nullptr,
                  wr0, wc0, lane, tid);
        const float* bb = ph ? b2 : b1;
        float* CC = ph ? C2 : C1;
#pragma unroll
        for (int mg = 0; mg < 2; mg++) {
            int ra = r0 + wr0 + mg * 16 + g, rb = ra + 8;
#pragma unroll
            for (int ng = 0; ng < 4; ng++) {
                int col = wc0 + ng * 8 + 2 * tig;
                float bv0 = bb[col], bv1 = bb[col + 1];
                if (ra < nrows)
                    *(float2*)(CC + (size_t)ra * FDIM + col) =
                        make_float2(actf(acc[mg][ng][0] + bv0), actf(acc[mg][ng][1] + bv1));
                if (rb < nrows)
                    *(float2*)(CC + (size_t)rb * FDIM + col) =
                        make_float2(actf(acc[mg][ng][2] + bv0), actf(acc[mg][ng][3] + bv1));
            }
        }
    }
    CP_WAIT0();
}

// ---- mega: full post-message chain for 64 atoms (13 matrices + outblock) ----
__global__ void __launch_bounds__(256, 1) mega_chain(
    const uint32_t* __restrict__ wbf, int b,
    const float* __restrict__ rib1, const float* __restrict__ rib2,
    const float* __restrict__ db, const float* __restrict__ uvec,
    const float* __restrict__ rab1, const float* __restrict__ rab2,
    const float* __restrict__ rob1, const float* __restrict__ rob2,
    const float* __restrict__ outW,
    const float* __restrict__ mbuf, float* __restrict__ xbuf,
    float* __restrict__ Ea, float* __restrict__ Qa,
    float* __restrict__ l2buf, float* __restrict__ nh, int nrows) {
    extern __shared__ uint32_t sm[];
    float* smf = (float*)sm;
    __shared__ float nharr[8];
    const int tid = threadIdx.x, lane = tid & 31, wid = tid >> 5;
    const int wr0 = (wid >> 2) * 32, wc0 = (wid & 3) * 32;
    const int r0 = blockIdx.x * 64;
    const int g = lane >> 2, tig = lane & 3;

    const uint32_t* mats[13] = {
        wbf + (size_t)(10 + b * 3) * MATW, wbf + (size_t)(25 + b * 3) * MATW,
        wbf + (size_t)(11 + b * 3) * MATW, wbf + (size_t)(26 + b * 3) * MATW,
        wbf + (size_t)(12 + b * 3) * MATW, wbf + (size_t)(27 + b * 3) * MATW,
        wbf + (size_t)(40 + b) * MATW,
        wbf + (size_t)(45 + b * 2) * MATW, wbf + (size_t)(55 + b * 2) * MATW,
        wbf + (size_t)(46 + b * 2) * MATW, wbf + (size_t)(56 + b * 2) * MATW,
        wbf + (size_t)(65 + b) * MATW, wbf + (size_t)(70 + b) * MATW
    };
    const float* B1S[6] = { rib1 + (b * 3 + 0) * 128, rib1 + (b * 3 + 1) * 128,
                            rib1 + (b * 3 + 2) * 128, rab1 + (b * 2 + 0) * 128,
                            rab1 + (b * 2 + 1) * 128, rob1 + b * 128 };
    const float* B2S[6] = { rib2 + (b * 3 + 0) * 128, rib2 + (b * 3 + 1) * 128,
                            rib2 + (b * 3 + 2) * 128, rab2 + (b * 2 + 0) * 128,
                            rab2 + (b * 2 + 1) * 128, rob2 + b * 128 };

    prefetch_plane(sm, MG_B0, mats[0], tid); CP_COMMIT();
    prefetch_plane(sm, MG_B1, mats[0] + WPLANE, tid); CP_COMMIT();

    // load m/x tiles, stage A = act(m)
#pragma unroll
    for (int i = 0; i < 8; i++) {
        int v = tid + i * 256;
        int row = v >> 5, c4 = v & 31;
        float4 mv = make_float4(0.f, 0.f, 0.f, 0.f), xv = mv;
        if (r0 + row < nrows) {
            mv = *(const float4*)(mbuf + (size_t)(r0 + row) * FDIM + c4 * 4);
            xv = *(const float4*)(xbuf + (size_t)(r0 + row) * FDIM + c4 * 4);
        }
        *(float4*)&smf[MG_XM + row * 132 + c4 * 4] = mv;
        *(float4*)&smf[MG_XX + row * 132 + c4 * 4] = xv;
        float a0 = actf(mv.x), a1 = actf(mv.y), a2 = actf(mv.z), a3 = actf(mv.w);
        sm[MG_AHI + row * PW + 2 * c4]     = pack_hi(a0, a1);
        sm[MG_AHI + row * PW + 2 * c4 + 1] = pack_hi(a2, a3);
        sm[MG_ALO + row * PW + 2 * c4]     = pack_lo(a0, a1);
        sm[MG_ALO + row * PW + 2 * c4 + 1] = pack_lo(a2, a3);
    }

    float acc[2][4][4];

    auto ep_h = [&](const float* b1p) {
#pragma unroll
        for (int mg = 0; mg < 2; mg++) {
            int ra = wr0 + mg * 16 + g, rb = ra + 8;
#pragma unroll
            for (int ng = 0; ng < 4; ng++) {
                int col = wc0 + ng * 8 + 2 * tig;
                float bv0 = b1p[col], bv1 = b1p[col + 1];
                float h0 = actf(acc[mg][ng][0] + bv0), h1 = actf(acc[mg][ng][1] + bv1);
                float h2 = actf(acc[mg][ng][2] + bv0), h3 = actf(acc[mg][ng][3] + bv1);
                int wa = ra * PW + (col >> 1), wb = rb * PW + (col >> 1);
                sm[MG_AHI + wa] = pack_hi(h0, h1); sm[MG_ALO + wa] = pack_lo(h0, h1);
                sm[MG_AHI + wb] = pack_hi(h2, h3); sm[MG_ALO + wb] = pack_lo(h2, h3);
            }
        }
    };

    auto ep_res2 = [&](int toff, const float* b2p, float* gout) {
#pragma unroll
        for (int mg = 0; mg < 2; mg++) {
            int ra = wr0 + mg * 16 + g, rb = ra + 8;
#pragma unroll
            for (int ng = 0; ng < 4; ng++) {
                int col = wc0 + ng * 8 + 2 * tig;
                float bv0 = b2p[col], bv1 = b2p[col + 1];
                float2 t0 = *(float2*)&smf[toff + ra * 132 + col];
                float2 t1 = *(float2*)&smf[toff + rb * 132 + col];
                t0.x += acc[mg][ng][0] + bv0; t0.y += acc[mg][ng][1] + bv1;
                t1.x += acc[mg][ng][2] + bv0; t1.y += acc[mg][ng][3] + bv1;
                *(float2*)&smf[toff + ra * 132 + col] = t0;
                *(float2*)&smf[toff + rb * 132 + col] = t1;
                int wa = ra * PW + (col >> 1), wb = rb * PW + (col >> 1);
                float a0 = actf(t0.x), a1 = actf(t0.y), a2 = actf(t1.x), a3 = actf(t1.y);
                sm[MG_AHI + wa] = pack_hi(a0, a1); sm[MG_ALO + wa] = pack_lo(a0, a1);
                sm[MG_AHI + wb] = pack_hi(a2, a3); sm[MG_ALO + wb] = pack_lo(a2, a3);
                if (gout) {
                    if (r0 + ra < nrows) *(float2*)(gout + (size_t)(r0 + ra) * FDIM + col) = t0;
                    if (r0 + rb < nrows) *(float2*)(gout + (size_t)(r0 + rb) * FDIM + col) = t1;
                }
            }
        }
    };

    auto ep_dw = [&]() {
        const float* dbp = db + b * 128;
        const float* uvp = uvec + b * 128;
#pragma unroll
        for (int mg = 0; mg < 2; mg++) {
            int ra = wr0 + mg * 16 + g, rb = ra + 8;
#pragma unroll
            for (int ng = 0; ng < 4; ng++) {
                int col = wc0 + ng * 8 + 2 * tig;
                float bv0 = dbp[col], bv1 = dbp[col + 1];
                float u0 = uvp[col], u1 = uvp[col + 1];
                float2 t0 = *(float2*)&smf[MG_XX + ra * 132 + col];
                float2 t1 = *(float2*)&smf[MG_XX + rb * 132 + col];
                t0.x = u0 * t0.x + acc[mg][ng][0] + bv0; t0.y = u1 * t0.y + acc[mg][ng][1] + bv1;
                t1.x = u0 * t1.x + acc[mg][ng][2] + bv0; t1.y = u1 * t1.y + acc[mg][ng][3] + bv1;
                *(float2*)&smf[MG_XX + ra * 132 + col] = t0;
                *(float2*)&smf[MG_XX + rb * 132 + col] = t1;
                int wa = ra * PW + (col >> 1), wb = rb * PW + (col >> 1);
                float a0 = actf(t0.x), a1 = actf(t0.y), a2 = actf(t1.x), a3 = actf(t1.y);
                sm[MG_AHI + wa] = pack_hi(a0, a1); sm[MG_ALO + wa] = pack_lo(a0, a1);
                sm[MG_AHI + wb] = pack_hi(a2, a3); sm[MG_ALO + wb] = pack_lo(a2, a3);
            }
        }
    };

    auto ep_o = [&](const float* b2p) {
#pragma unroll
        for (int mg = 0; mg < 2; mg++) {
            int ra = wr0 + mg * 16 + g, rb = ra + 8;
#pragma unroll
            for (int ng = 0; ng < 4; ng++) {
                int col = wc0 + ng * 8 + 2 * tig;
                float bv0 = b2p[col], bv1 = b2p[col + 1];
                float2 x0 = *(float2*)&smf[MG_XX + ra * 132 + col];
                float2 x1 = *(float2*)&smf[MG_XX + rb * 132 + col];
                *(float2*)&smf[MG_XM + ra * 132 + col] =
                    make_float2(x0.x + acc[mg][ng][0] + bv0, x0.y + acc[mg][ng][1] + bv1);
                *(float2*)&smf[MG_XM + rb * 132 + col] =
                    make_float2(x1.x + acc[mg][ng][2] + bv0, x1.y + acc[mg][ng][3] + bv1);
            }
        }
    };

#define RUN_MAT_I(i) do { zero_acc(acc); \
    do_matrix(sm, acc, MG_AHI, MG_ALO, MG_B0, MG_B1, mats[i], mats[i] + WPLANE, \
              wr0, wc0, lane, tid); } while (0)
#define RUN_MAT_LAST() do { zero_acc(acc); \
    do_matrix(sm, acc, MG_AHI, MG_ALO, MG_B0, MG_B1, nullptr, nullptr, \
              wr0, wc0, lane, tid); } while (0)

    RUN_MAT_I(1);   ep_h(B1S[0]);
    RUN_MAT_I(2);   ep_res2(MG_XM, B2S[0], nullptr);
    RUN_MAT_I(3);   ep_h(B1S[1]);
    RUN_MAT_I(4);   ep_res2(MG_XM, B2S[1], nullptr);
    RUN_MAT_I(5);   ep_h(B1S[2]);
    RUN_MAT_I(6);   ep_res2(MG_XM, B2S[2], nullptr);
    RUN_MAT_I(7);   ep_dw();
    RUN_MAT_I(8);   ep_h(B1S[3]);
    RUN_MAT_I(9);   ep_res2(MG_XX, B2S[3], nullptr);
    RUN_MAT_I(10);  ep_h(B1S[4]);
    RUN_MAT_I(11);  ep_res2(MG_XX, B2S[4], xbuf);
    RUN_MAT_I(12);  ep_h(B1S[5]);
    RUN_MAT_LAST(); ep_o(B2S[5]);
    CP_WAIT0();
    __syncthreads();

    // outblock: warp wid handles rows wid*8..wid*8+7 of o (in XM tile)
    const float* ow = outW + b * 256;
    float nhsum = 0.f;
#pragma unroll
    for (int qq = 0; qq < 8; qq++) {
        int r = wid * 8 + qq;
        int row = r0 + r;
        float4 ov = *(float4*)&smf[MG_XM + r * 132 + lane * 4];
        float a0 = actf(ov.x), a1 = actf(ov.y), a2 = actf(ov.z), a3 = actf(ov.w);
        int c = lane * 8;   // = (lane*4)*2
        float e  = a0 * ow[c] + a1 * ow[c + 2] + a2 * ow[c + 4] + a3 * ow[c + 6];
        float qv = a0 * ow[c + 1] + a1 * ow[c + 3] + a2 * ow[c + 5] + a3 * ow[c + 7];
#pragma unroll
        for (int s = 16; s; s >>= 1) {
            e  += __shfl_xor_sync(0xffffffffu, e, s);
            qv += __shfl_xor_sync(0xffffffffu, qv, s);
        }
        if (lane == 0 && row < nrows) {
            Ea[row] += e; Qa[row] += qv;
            float e2 = e * e, q2 = qv * qv;
            if (b > 0) {
                float le = l2buf[2 * row], lq = l2buf[2 * row + 1];
                nhsum += e2 / (e2 + le + 1e-7f) + q2 / (q2 + lq + 1e-7f);
            }
            l2buf[2 * row] = e2; l2buf[2 * row + 1] = q2;
        }
    }
    if (lane == 0) nharr[wid] = nhsum;
    __syncthreads();
    if (tid == 0) {
        float s2 = 0.f;
#pragma unroll
        for (int i = 0; i < 8; i++) s2 += nharr[i];
        atomicAdd(nh, s2);
    }
}

// ---- fused weight conversion ----
struct WSrc { const float* p[9]; };

__global__ void conv_weights_all(WSrc s, uint32_t* __restrict__ dst) {
    int gid = blockIdx.x * blockDim.x + threadIdx.x;
    if (gid >= 75 * 16384) return;
    int m = gid >> 14, e = gid & 16383;
    int grp, loc;
    if      (m < 5)  { grp = 0; loc = m; }
    else if (m < 10) { grp = 1; loc = m - 5; }
    else if (m < 25) { grp = 2; loc = m - 10; }
    else if (m < 40) { grp = 3; loc = m - 25; }
    else if (m < 45) { grp = 4; loc = m - 40; }
    else if (m < 55) { grp = 5; loc = m - 45; }
    else if (m < 65) { grp = 6; loc = m - 55; }
    else if (m < 70) { grp = 7; loc = m - 65; }
    else             { grp = 8; loc = m - 70; }
    float x = s.p[grp][loc * 16384 + e];
    int k = e >> 7, n = e & 127;
    __nv_bfloat16 hi = __float2bfloat16(x);
    __nv_bfloat16 lo = __float2bfloat16(x - __bfloat162float(hi));
    char* bp = (char*)(dst + (size_t)m * MATW);
    *(__nv_bfloat16*)(bp + n * 272 + k * 2)         = hi;
    *(__nv_bfloat16*)(bp + 34816 + n * 272 + k * 2) = lo;
}

__global__ void conv_k2f(const float* __restrict__ src, uint32_t* __restrict__ dst) {
    int gid = blockIdx.x * blockDim.x + threadIdx.x;
    if (gid >= 5 * 4096) return;
    int b = gid >> 12, r = gid & 4095;
    int n = r >> 5, w = r & 31;
    const float* s = src + b * 8192;
    float x0 = s[(2 * w) * 128 + n], x1 = s[(2 * w + 1) * 128 + n];
    dst[b * 9216 + n * MPW + w]        = pack_hi(x0, x1);
    dst[b * 9216 + 4608 + n * MPW + w] = pack_lo(x0, x1);
}

__global__ void init_kernel(const int* __restrict__ Z, const float* __restrict__ emb,
                            float* __restrict__ x) {
    int idx = blockIdx.x * blockDim.x + threadIdx.x;
    if (idx < NATOMS * FDIM) {
        int n = idx >> 7, f = idx & 127;
        x[idx] = emb[Z[n] * FDIM + f];
    }
}

__global__ void pair_kernel(const float* __restrict__ R, const int* __restrict__ idx_i,
                            const int* __restrict__ idx_j, const float* __restrict__ cent,
                            const float* __restrict__ wid,
                            uint32_t* __restrict__ rbfh, uint32_t* __restrict__ rbfl,
                            float* __restrict__ Dij_out) {
    int gid = blockIdx.x * blockDim.x + threadIdx.x;
    int p = gid >> 5, w = gid & 31;
    if (p >= NPAIRS) return;
    int i = idx_i[p], j = idx_j[p];
    float dx = R[i * 3 + 0] - R[j * 3 + 0];
    float dy = R[i * 3 + 1] - R[j * 3 + 1];
    float dz = R[i * 3 + 2] - R[j * 3 + 2];
    float D = sqrtf(fmaxf(dx * dx + dy * dy + dz * dz, 0.f));
    if (w == 0) Dij_out[p] = D;
    float xr = D * 0.1f;
    float cut = 0.f;
    if (xr < 1.f) {
        float x3 = xr * xr * xr, x4 = x3 * xr, x5 = x4 * xr;
        cut = 1.f - 6.f * x5 + 15.f * x4 - 10.f * x3;
    }
    float ed = __expf(-D);
    float t0 = ed - cent[2 * w], t1 = ed - cent[2 * w + 1];
    float r0 = cut * __expf(-wid[2 * w] * t0 * t0);
    float r1 = cut * __expf(-wid[2 * w + 1] * t1 * t1);
    rbfh[p * 32 + w] = pack_hi(r0, r1);
    rbfl[p * 32 + w] = pack_lo(r0, r1);
}

__global__ void __launch_bounds__(256, 2) message_mma(
    const uint32_t* __restrict__ rbfh, const uint32_t* __restrict__ rbfl,
    const uint32_t* __restrict__ k2f, const float* __restrict__ xj,
    const int* __restrict__ idx_i, const int* __restrict__ idx_j,
    float* __restrict__ m) {
    extern __shared__ uint32_t sm[];
    float* gf = (float*)(sm + OFF_G);
    const int tid = threadIdx.x, lane = tid & 31, wid = tid >> 5;
    const int g = lane >> 2, tig = lane & 3;
    const int wr0 = (wid >> 2) * 32, wc0 = (wid & 3) * 32;

    {
        const uint4* kv = (const uint4*)k2f;
        uint4* sv = (uint4*)sm;
#pragma unroll
        for (int i = 0; i < 9; i++) sv[tid + i * 256] = kv[tid + i * 256];
    }

    for (int ch = blockIdx.x; ch < NCH; ch += gridDim.x) {
        const int p0 = ch * 64;
        __syncthreads();
#pragma unroll
        for (int i = 0; i < 8; i++) {
            int v = tid + i * 256;
            int r = v >> 5, w = v & 31;
            sm[OFF_RBFH + r * MPW + w] = rbfh[p0 * 32 + v];
            sm[OFF_RBFL + r * MPW + w] = rbfl[p0 * 32 + v];
        }
        __syncthreads();

        float acc[2][4][4];
        zero_acc(acc);
#pragma unroll
        for (int ks = 0; ks < 4; ks++) {
            const int kw = ks * 8 + tig;
            uint32_t ah[2][4], al[2][4];
#pragma unroll
            for (int mg = 0; mg < 2; mg++) {
                int ba = OFF_RBFH + (wr0 + mg * 16 + g) * MPW + kw;
                ah[mg][0] = sm[ba];            ah[mg][1] = sm[ba + 8 * MPW];
                ah[mg][2] = sm[ba + 4];        ah[mg][3] = sm[ba + 8 * MPW + 4];
                int bb2 = ba + (OFF_RBFL - OFF_RBFH);
                al[mg][0] = sm[bb2];            al[mg][1] = sm[bb2 + 8 * MPW];
                al[mg][2] = sm[bb2 + 4];        al[mg][3] = sm[bb2 + 8 * MPW + 4];
            }
#pragma unroll
            for (int ng = 0; ng < 4; ng++) {
                int nb = (wc0 + ng * 8 + g) * MPW + kw;
                uint32_t bh[2] = { sm[nb],        sm[nb + 4] };
                uint32_t bl[2] = { sm[nb + 4608], sm[nb + 4608 + 4] };
#pragma unroll
                for (int mg = 0; mg < 2; mg++) {
                    mma_bf16(acc[mg][ng], ah[mg], bh);
                    mma_bf16(acc[mg][ng], ah[mg], bl);
                    mma_bf16(acc[mg][ng], al[mg], bh);
                }
            }
        }

#pragma unroll
        for (int mg = 0; mg < 2; mg++) {
            int row = wr0 + mg * 16 + g;
#pragma unroll
            for (int ng = 0; ng < 4; ng++) {
                int col = wc0 + ng * 8 + 2 * tig;
                *(float2*)&gf[row * 132 + col]       = make_float2(acc[mg][ng][0], acc[mg][ng][1]);
                *(float2*)&gf[(row + 8) * 132 + col] = make_float2(acc[mg][ng][2], acc[mg][ng][3]);
            }
        }
        __syncthreads();

#pragma unroll
        for (int q = 0; q < 8; q++) {
            int r = wid * 8 + q, p = p0 + r;
            int i = idx_i[p], j = idx_j[p];
            float4 gv = *(const float4*)&gf[r * 132 + lane * 4];
            float4 xv = *(const float4*)(xj + (size_t)j * FDIM + lane * 4);
            red_add_f4(m + (size_t)i * FDIM + lane * 4,
                       make_float4(gv.x * xv.x, gv.y * xv.y, gv.z * xv.z, gv.w * xv.w));
        }
    }
}

__global__ void final_kernel(const int* __restrict__ Z, const float* __restrict__ Ea,
                             const float* __restrict__ Qa, const float* __restrict__ nh,
                             const float* __restrict__ Es, const float* __restrict__ Eh,
                             const float* __restrict__ Qs, const float* __restrict__ Qh,
                             float* __restrict__ out) {
    int n = blockIdx.x * blockDim.x + threadIdx.x;
    if (n < NATOMS) {
        int z = Z[n];
        out[n]          = Es[z] * Ea[n] + Eh[z];
        out[NATOMS + n] = Qs[z] * Qa[n] + Qh[z];
    }
    if (n == 0) out[2 * NATOMS + NPAIRS] = *nh / (2.f * NATOMS);
}

// ---------------- launch ----------------
extern "C" void kernel_launch(void* const* d_in, const int* in_sizes, int n_in,
                              void* d_out, int out_size) {
    const int*   Z      = (const int*)  d_in[0];
    const float* R      = (const float*)d_in[1];
    const int*   idx_i  = (const int*)  d_in[2];
    const int*   idx_j  = (const int*)  d_in[3];
    const float* emb    = (const float*)d_in[4];
    const float* cent   = (const float*)d_in[5];
    const float* wid    = (const float*)d_in[6];
    const float* k2f    = (const float*)d_in[7];
    const float* Wi     = (const float*)d_in[8];
    const float* bi     = (const float*)d_in[9];
    const float* Wj     = (const float*)d_in[10];
    const float* bj     = (const float*)d_in[11];
    const float* riW1   = (const float*)d_in[12];
    const float* rib1   = (const float*)d_in[13];
    const float* riW2   = (const float*)d_in[14];
    const float* rib2   = (const float*)d_in[15];
    const float* dW     = (const float*)d_in[16];
    const float* db     = (const float*)d_in[17];
    const float* u      = (const float*)d_in[18];
    const float* raW1   = (const float*)d_in[19];
    const float* rab1   = (const float*)d_in[20];
    const float* raW2   = (const float*)d_in[21];
    const float* rab2   = (const float*)d_in[22];
    const float* roW1   = (const float*)d_in[23];
    const float* rob1   = (const float*)d_in[24];
    const float* roW2   = (const float*)d_in[25];
    const float* rob2   = (const float*)d_in[26];
    const float* outW   = (const float*)d_in[27];
    const float* Escale = (const float*)d_in[28];
    const float* Eshift = (const float*)d_in[29];
    const float* Qscale = (const float*)d_in[30];
    const float* Qshift = (const float*)d_in[31];
    float* out = (float*)d_out;

    float *x, *xjb, *m, *Ea, *Qa, *l2, *nh;
    uint32_t *wbf, *rbfh, *rbfl, *k2fb;
    cudaGetSymbolAddress((void**)&rbfh, g_rbfh);
    cudaGetSymbolAddress((void**)&rbfl, g_rbfl);
    cudaGetSymbolAddress((void**)&k2fb, g_k2fb);
    cudaGetSymbolAddress((void**)&x,   g_x);
    cudaGetSymbolAddress((void**)&xjb, g_xj);
    cudaGetSymbolAddress((void**)&m,   g_m);
    cudaGetSymbolAddress((void**)&Ea,  g_Ea);
    cudaGetSymbolAddress((void**)&Qa,  g_Qa);
    cudaGetSymbolAddress((void**)&l2,  g_l2);
    cudaGetSymbolAddress((void**)&nh,  g_nh);
    cudaGetSymbolAddress((void**)&wbf, g_wbf);

    cudaFuncSetAttribute(gemm_dual_mma, cudaFuncAttributeMaxDynamicSharedMemorySize, SM_DUAL);
    cudaFuncSetAttribute(mega_chain,    cudaFuncAttributeMaxDynamicSharedMemorySize, SM_MEGA);
    cudaFuncSetAttribute(message_mma,   cudaFuncAttributeMaxDynamicSharedMemorySize, SM_MSG);

    cudaMemsetAsync(Ea, 0, NATOMS * sizeof(float));
    cudaMemsetAsync(Qa, 0, NATOMS * sizeof(float));
    cudaMemsetAsync(nh, 0, sizeof(float));

    WSrc ws;
    ws.p[0] = Wi;   ws.p[1] = Wj;   ws.p[2] = riW1; ws.p[3] = riW2; ws.p[4] = dW;
    ws.p[5] = raW1; ws.p[6] = raW2; ws.p[7] = roW1; ws.p[8] = roW2;
    conv_weights_all<<<(75 * 16384 + 255) / 256, 256>>>(ws, wbf);
    conv_k2f<<<(5 * 4096 + 255) / 256, 256>>>(k2f, k2fb);

    init_kernel<<<(NATOMS * FDIM + 255) / 256, 256>>>(Z, emb, x);
    pair_kernel<<<(NPAIRS * 32 + 255) / 256, 256>>>(R, idx_i, idx_j, cent, wid,
                                                    rbfh, rbfl, out + 2 * NATOMS);

    const int GB = (NATOMS + 63) / 64;  // 157
    for (int b = 0; b < NB; b++) {
        gemm_dual_mma<<<GB, 256, SM_DUAL>>>(x, wbf + (size_t)(0 + b) * MATW,
                                            wbf + (size_t)(5 + b) * MATW,
                                            bi + b * 128, bj + b * 128, m, xjb, NATOMS);
        message_mma<<<296, 256, SM_MSG>>>(rbfh, rbfl, k2fb + (size_t)b * 9216,
                                          xjb, idx_i, idx_j, m);
        mega_chain<<<GB, 256, SM_MEGA>>>(wbf, b, rib1, rib2, db, u, rab1, rab2,
                                         rob1, rob2, outW, m, x, Ea, Qa, l2, nh, NATOMS);
    }
    final_kernel<<<(NATOMS + 255) / 256, 256>>>(Z, Ea, Qa, nh, Escale, Eshift,
                                                Qscale, Qshift, out);
}

// round 13
// speedup vs baseline: 1.5682x; 1.5682x over previous
#include <cuda_runtime.h>
#include <cuda_bf16.h>
#include <cstdint>

#define NATOMS 10000
#define NPAIRS 320000
#define FDIM 128
#define KDIM 64
#define NB 5
#define NRI 3
#define NRA 2

// bf16 padded plane: 128 bf16/row = 64 words + 4 pad = 68 words
#define PW 68
#define A_LO 4352
#define WPLANE 8704          // one plane = 128 rows * 68 words
#define MATW 17408           // matrix = hi+lo planes
#define WS0 8704             // single W slot (hi at WS0, lo at WS0+WPLANE)
#define SM_DENSE (26112 * 4) // A planes (34816B) + one W slot (69632B) = 104448B -> 2 CTAs/SM

// message MMA smem
#define MPW 36
#define OFF_RBFH 9216
#define OFF_RBFL 11520
#define OFF_G 13824
#define SM_MSG ((13824 + 8448) * 4)
#define NCH (NPAIRS / 64)

// ---------------- scratch ----------------
__device__ uint32_t g_rbfh[NPAIRS * 32];
__device__ uint32_t g_rbfl[NPAIRS * 32];
__device__ uint32_t g_k2fb[5 * 9216];
__device__ float g_x [NATOMS * FDIM];
__device__ float g_xj[NATOMS * FDIM];
__device__ float g_m [NATOMS * FDIM];
__device__ float g_o [NATOMS * FDIM];
__device__ float g_Ea[NATOMS];
__device__ float g_Qa[NATOMS];
__device__ float g_l2[NATOMS * 2];
__device__ float g_nh;
__device__ uint32_t g_wbf[75 * MATW];

__device__ __forceinline__ float actf(float x) {
    return fmaxf(x, 0.f) + log1pf(__expf(-fabsf(x))) - 0.69314718055994531f;
}

__device__ __forceinline__ void red_add_f4(float* p, float4 v) {
    asm volatile("red.global.add.v4.f32 [%0], {%1,%2,%3,%4};"
                 :: "l"(p), "f"(v.x), "f"(v.y), "f"(v.z), "f"(v.w) : "memory");
}

__device__ __forceinline__ uint32_t pack_hi(float a, float b) {
    __nv_bfloat16 h0 = __float2bfloat16(a), h1 = __float2bfloat16(b);
    return (uint32_t)__bfloat16_as_ushort(h0) | ((uint32_t)__bfloat16_as_ushort(h1) << 16);
}
__device__ __forceinline__ uint32_t pack_lo(float a, float b) {
    __nv_bfloat16 h0 = __float2bfloat16(a), h1 = __float2bfloat16(b);
    float r0 = a - __bfloat162float(h0), r1 = b - __bfloat162float(h1);
    __nv_bfloat16 l0 = __float2bfloat16(r0), l1 = __float2bfloat16(r1);
    return (uint32_t)__bfloat16_as_ushort(l0) | ((uint32_t)__bfloat16_as_ushort(l1) << 16);
}

__device__ __forceinline__ void mma_bf16(float c[4], const uint32_t a[4], const uint32_t b[2]) {
    asm volatile(
        "mma.sync.aligned.m16n8k16.row.col.f32.bf16.bf16.f32 "
        "{%0,%1,%2,%3}, {%4,%5,%6,%7}, {%8,%9}, {%0,%1,%2,%3};"
        : "+f"(c[0]), "+f"(c[1]), "+f"(c[2]), "+f"(c[3])
        : "r"(a[0]), "r"(a[1]), "r"(a[2]), "r"(a[3]), "r"(b[0]), "r"(b[1]));
}

#define CP_COMMIT() asm volatile("cp.async.commit_group;" ::: "memory")
#define CP_WAIT0()  asm volatile("cp.async.wait_group 0;" ::: "memory")

// stream one full weight matrix (hi+lo planes = 4352 uint4) into the W slot
__device__ __forceinline__ void prefetch_mat(uint32_t* sm, const uint32_t* __restrict__ g,
                                             int tid) {
    uint32_t sb = (uint32_t)__cvta_generic_to_shared(sm + WS0);
#pragma unroll
    for (int i = 0; i < 17; i++) {
        int v = tid + i * 256;
        asm volatile("cp.async.cg.shared.global [%0], [%1], 16;"
                     :: "r"(sb + v * 16), "l"(g + v * 4) : "memory");
    }
    CP_COMMIT();
}

// ---- A tile from gmem: fp32 -> act -> bf16 hi/lo planes at offsets 0 / A_LO ----
__device__ __forceinline__ void conv_A(const float* __restrict__ A, uint32_t* sm,
                                       int tid, int r0, int nrows) {
#pragma unroll 4
    for (int i = 0; i < 16; i++) {
        int v = tid + i * 256;
        int row = v >> 6, kp = v & 63;
        float2 av = make_float2(0.f, 0.f);
        if (r0 + row < nrows) av = *(const float2*)(A + (size_t)(r0 + row) * FDIM + kp * 2);
        av.x = actf(av.x); av.y = actf(av.y);
        sm[row * PW + kp]        = pack_hi(av.x, av.y);
        sm[A_LO + row * PW + kp] = pack_lo(av.x, av.y);
    }
}

// ---- warp k-loop: acc += A @ W (bf16 hi/lo 3-combo), warp tile 32x32, A at 0/A_LO ----
__device__ __forceinline__ void kloop(const uint32_t* __restrict__ sm, int woff,
                                      int wr0, int wc0, int lane, float acc[2][4][4]) {
    const int g = lane >> 2, tig = lane & 3;
#pragma unroll
    for (int ks = 0; ks < 8; ks++) {
        const int kw = ks * 8 + tig;
        uint32_t ah[2][4], al[2][4];
#pragma unroll
        for (int mg = 0; mg < 2; mg++) {
            int b = (wr0 + mg * 16 + g) * PW + kw;
            ah[mg][0] = sm[b];            ah[mg][1] = sm[b + 8 * PW];
            ah[mg][2] = sm[b + 4];        ah[mg][3] = sm[b + 8 * PW + 4];
            al[mg][0] = sm[A_LO + b];     al[mg][1] = sm[A_LO + b + 8 * PW];
            al[mg][2] = sm[A_LO + b + 4]; al[mg][3] = sm[A_LO + b + 8 * PW + 4];
        }
#pragma unroll
        for (int ng = 0; ng < 4; ng++) {
            int nb = woff + (wc0 + ng * 8 + g) * PW + kw;
            uint32_t bh[2] = { sm[nb],          sm[nb + 4] };
            uint32_t bl[2] = { sm[nb + WPLANE], sm[nb + WPLANE + 4] };
#pragma unroll
            for (int mg = 0; mg < 2; mg++) {
                mma_bf16(acc[mg][ng], ah[mg], bh);
                mma_bf16(acc[mg][ng], ah[mg], bl);
                mma_bf16(acc[mg][ng], al[mg], bh);
            }
        }
    }
}

__device__ __forceinline__ void zero_acc(float acc[2][4][4]) {
#pragma unroll
    for (int a = 0; a < 2; a++)
#pragma unroll
        for (int b = 0; b < 4; b++)
#pragma unroll
            for (int c = 0; c < 4; c++) acc[a][b][c] = 0.f;
}

// ---- dual: C1 = act(act(A)@W1+b1), C2 = act(act(A)@W2+b2); W streamed, 2 CTAs/SM ----
__global__ void __launch_bounds__(256, 2) gemm_dual_mma(
    const float* __restrict__ A, const uint32_t* __restrict__ w1,
    const uint32_t* __restrict__ w2, const float* __restrict__ b1,
    const float* __restrict__ b2, float* __restrict__ C1, float* __restrict__ C2, int nrows) {
    extern __shared__ uint32_t sm[];
    const int tid = threadIdx.x, lane = tid & 31, wid = tid >> 5;
    const int wr0 = (wid >> 2) * 32, wc0 = (wid & 3) * 32;
    const int r0 = blockIdx.x * 64;
    const int g = lane >> 2, tig = lane & 3;

    prefetch_mat(sm, w1, tid);
    conv_A(A, sm, tid, r0, nrows);
    CP_WAIT0(); __syncthreads();

    float acc[2][4][4];
#pragma unroll
    for (int ph = 0; ph < 2; ph++) {
        zero_acc(acc);
        kloop(sm, WS0, wr0, wc0, lane, acc);
        __syncthreads();                      // all W reads done
        if (ph == 0) prefetch_mat(sm, w2, tid);
        const float* bb = ph ? b2 : b1;
        float* CC = ph ? C2 : C1;
#pragma unroll
        for (int mg = 0; mg < 2; mg++) {
            int ra = r0 + wr0 + mg * 16 + g, rb = ra + 8;
#pragma unroll
            for (int ng = 0; ng < 4; ng++) {
                int col = wc0 + ng * 8 + 2 * tig;
                float bv0 = bb[col], bv1 = bb[col + 1];
                if (ra < nrows)
                    *(float2*)(CC + (size_t)ra * FDIM + col) =
                        make_float2(actf(acc[mg][ng][0] + bv0), actf(acc[mg][ng][1] + bv1));
                if (rb < nrows)
                    *(float2*)(CC + (size_t)rb * FDIM + col) =
                        make_float2(actf(acc[mg][ng][2] + bv0), actf(acc[mg][ng][3] + bv1));
            }
        }
        if (ph == 0) { CP_WAIT0(); __syncthreads(); }
    }
}

// ---- resid: C = A + act(act(A)@W1+b1)@W2 + b2; W streamed, 2 CTAs/SM ----
__global__ void __launch_bounds__(256, 2) gemm_resid_mma(
    const float* __restrict__ A, const uint32_t* __restrict__ w1,
    const uint32_t* __restrict__ w2, const float* __restrict__ b1,
    const float* __restrict__ b2, float* __restrict__ C, int nrows) {
    extern __shared__ uint32_t sm[];
    const int tid = threadIdx.x, lane = tid & 31, wid = tid >> 5;
    const int wr0 = (wid >> 2) * 32, wc0 = (wid & 3) * 32;
    const int r0 = blockIdx.x * 64;
    const int g = lane >> 2, tig = lane & 3;

    prefetch_mat(sm, w1, tid);
    conv_A(A, sm, tid, r0, nrows);
    CP_WAIT0(); __syncthreads();

    float acc[2][4][4];
    zero_acc(acc);
    kloop(sm, WS0, wr0, wc0, lane, acc);
    __syncthreads();                          // A-plane reads + W1 reads done
    prefetch_mat(sm, w2, tid);                // stream W2 while epilogue runs

    // h = act(. + b1) -> back into A hi/lo planes
#pragma unroll
    for (int mg = 0; mg < 2; mg++) {
        int ra = wr0 + mg * 16 + g, rb = ra + 8;
#pragma unroll
        for (int ng = 0; ng < 4; ng++) {
            int col = wc0 + ng * 8 + 2 * tig;
            float bv0 = b1[col], bv1 = b1[col + 1];
            float h0 = actf(acc[mg][ng][0] + bv0), h1 = actf(acc[mg][ng][1] + bv1);
            float h2 = actf(acc[mg][ng][2] + bv0), h3 = actf(acc[mg][ng][3] + bv1);
            int wa = ra * PW + (col >> 1), wb = rb * PW + (col >> 1);
            sm[wa] = pack_hi(h0, h1); sm[A_LO + wa] = pack_lo(h0, h1);
            sm[wb] = pack_hi(h2, h3); sm[A_LO + wb] = pack_lo(h2, h3);
        }
    }
    CP_WAIT0(); __syncthreads();

    zero_acc(acc);
    kloop(sm, WS0, wr0, wc0, lane, acc);

#pragma unroll
    for (int mg = 0; mg < 2; mg++) {
        int ra = r0 + wr0 + mg * 16 + g, rb = ra + 8;
#pragma unroll
        for (int ng = 0; ng < 4; ng++) {
            int col = wc0 + ng * 8 + 2 * tig;
            float bv0 = b2[col], bv1 = b2[col + 1];
            if (ra < nrows) {
                float2 a = *(const float2*)(A + (size_t)ra * FDIM + col);
                *(float2*)(C + (size_t)ra * FDIM + col) =
                    make_float2(a.x + acc[mg][ng][0] + bv0, a.y + acc[mg][ng][1] + bv1);
            }
            if (rb < nrows) {
                float2 a = *(const float2*)(A + (size_t)rb * FDIM + col);
                *(float2*)(C + (size_t)rb * FDIM + col) =
                    make_float2(a.x + acc[mg][ng][2] + bv0, a.y + acc[mg][ng][3] + bv1);
            }
        }
    }
}

// ---- dw: C = uvec*base + act(A)@W + bias; 2 CTAs/SM ----
__global__ void __launch_bounds__(256, 2) gemm_dw_mma(
    const float* __restrict__ A, const uint32_t* __restrict__ w,
    const float* __restrict__ bias, const float* __restrict__ base,
    const float* __restrict__ uvec, float* __restrict__ C, int nrows) {
    extern __shared__ uint32_t sm[];
    const int tid = threadIdx.x, lane = tid & 31, wid = tid >> 5;
    const int wr0 = (wid >> 2) * 32, wc0 = (wid & 3) * 32;
    const int r0 = blockIdx.x * 64;
    const int g = lane >> 2, tig = lane & 3;

    prefetch_mat(sm, w, tid);
    conv_A(A, sm, tid, r0, nrows);
    CP_WAIT0(); __syncthreads();

    float acc[2][4][4];
    zero_acc(acc);
    kloop(sm, WS0, wr0, wc0, lane, acc);

#pragma unroll
    for (int mg = 0; mg < 2; mg++) {
        int ra = r0 + wr0 + mg * 16 + g, rb = ra + 8;
#pragma unroll
        for (int ng = 0; ng < 4; ng++) {
            int col = wc0 + ng * 8 + 2 * tig;
            float bv0 = bias[col], bv1 = bias[col + 1];
            float u0 = uvec[col], u1 = uvec[col + 1];
            if (ra < nrows) {
                float2 x = *(const float2*)(base + (size_t)ra * FDIM + col);
                *(float2*)(C + (size_t)ra * FDIM + col) =
                    make_float2(u0 * x.x + acc[mg][ng][0] + bv0, u1 * x.y + acc[mg][ng][1] + bv1);
            }
            if (rb < nrows) {
                float2 x = *(const float2*)(base + (size_t)rb * FDIM + col);
                *(float2*)(C + (size_t)rb * FDIM + col) =
                    make_float2(u0 * x.x + acc[mg][ng][2] + bv0, u1 * x.y + acc[mg][ng][3] + bv1);
            }
        }
    }
}

// ---- fused weight conversion ----
struct WSrc { const float* p[9]; };

__global__ void conv_weights_all(WSrc s, uint32_t* __restrict__ dst) {
    int gid = blockIdx.x * blockDim.x + threadIdx.x;
    if (gid >= 75 * 16384) return;
    int m = gid >> 14, e = gid & 16383;
    int grp, loc;
    if      (m < 5)  { grp = 0; loc = m; }
    else if (m < 10) { grp = 1; loc = m - 5; }
    else if (m < 25) { grp = 2; loc = m - 10; }
    else if (m < 40) { grp = 3; loc = m - 25; }
    else if (m < 45) { grp = 4; loc = m - 40; }
    else if (m < 55) { grp = 5; loc = m - 45; }
    else if (m < 65) { grp = 6; loc = m - 55; }
    else if (m < 70) { grp = 7; loc = m - 65; }
    else             { grp = 8; loc = m - 70; }
    float x = s.p[grp][loc * 16384 + e];
    int k = e >> 7, n = e & 127;
    __nv_bfloat16 hi = __float2bfloat16(x);
    __nv_bfloat16 lo = __float2bfloat16(x - __bfloat162float(hi));
    char* bp = (char*)(dst + (size_t)m * MATW);
    *(__nv_bfloat16*)(bp + n * 272 + k * 2)         = hi;
    *(__nv_bfloat16*)(bp + 34816 + n * 272 + k * 2) = lo;
}

__global__ void conv_k2f(const float* __restrict__ src, uint32_t* __restrict__ dst) {
    int gid = blockIdx.x * blockDim.x + threadIdx.x;
    if (gid >= 5 * 4096) return;
    int b = gid >> 12, r = gid & 4095;
    int n = r >> 5, w = r & 31;
    const float* s = src + b * 8192;
    float x0 = s[(2 * w) * 128 + n], x1 = s[(2 * w + 1) * 128 + n];
    dst[b * 9216 + n * MPW + w]        = pack_hi(x0, x1);
    dst[b * 9216 + 4608 + n * MPW + w] = pack_lo(x0, x1);
}

__global__ void init_kernel(const int* __restrict__ Z, const float* __restrict__ emb,
                            float* __restrict__ x) {
    int idx = blockIdx.x * blockDim.x + threadIdx.x;
    if (idx < NATOMS * FDIM) {
        int n = idx >> 7, f = idx & 127;
        x[idx] = emb[Z[n] * FDIM + f];
    }
}

__global__ void pair_kernel(const float* __restrict__ R, const int* __restrict__ idx_i,
                            const int* __restrict__ idx_j, const float* __restrict__ cent,
                            const float* __restrict__ wid,
                            uint32_t* __restrict__ rbfh, uint32_t* __restrict__ rbfl,
                            float* __restrict__ Dij_out) {
    int gid = blockIdx.x * blockDim.x + threadIdx.x;
    int p = gid >> 5, w = gid & 31;
    if (p >= NPAIRS) return;
    int i = idx_i[p], j = idx_j[p];
    float dx = R[i * 3 + 0] - R[j * 3 + 0];
    float dy = R[i * 3 + 1] - R[j * 3 + 1];
    float dz = R[i * 3 + 2] - R[j * 3 + 2];
    float D = sqrtf(fmaxf(dx * dx + dy * dy + dz * dz, 0.f));
    if (w == 0) Dij_out[p] = D;
    float xr = D * 0.1f;
    float cut = 0.f;
    if (xr < 1.f) {
        float x3 = xr * xr * xr, x4 = x3 * xr, x5 = x4 * xr;
        cut = 1.f - 6.f * x5 + 15.f * x4 - 10.f * x3;
    }
    float ed = __expf(-D);
    float t0 = ed - cent[2 * w], t1 = ed - cent[2 * w + 1];
    float r0 = cut * __expf(-wid[2 * w] * t0 * t0);
    float r1 = cut * __expf(-wid[2 * w + 1] * t1 * t1);
    rbfh[p * 32 + w] = pack_hi(r0, r1);
    rbfl[p * 32 + w] = pack_lo(r0, r1);
}

__global__ void __launch_bounds__(256, 2) message_mma(
    const uint32_t* __restrict__ rbfh, const uint32_t* __restrict__ rbfl,
    const uint32_t* __restrict__ k2f, const float* __restrict__ xj,
    const int* __restrict__ idx_i, const int* __restrict__ idx_j,
    float* __restrict__ m) {
    extern __shared__ uint32_t sm[];
    float* gf = (float*)(sm + OFF_G);
    const int tid = threadIdx.x, lane = tid & 31, wid = tid >> 5;
    const int g = lane >> 2, tig = lane & 3;
    const int wr0 = (wid >> 2) * 32, wc0 = (wid & 3) * 32;

    {
        const uint4* kv = (const uint4*)k2f;
        uint4* sv = (uint4*)sm;
#pragma unroll
        for (int i = 0; i < 9; i++) sv[tid + i * 256] = kv[tid + i * 256];
    }

    for (int ch = blockIdx.x; ch < NCH; ch += gridDim.x) {
        const int p0 = ch * 64;
        __syncthreads();
#pragma unroll
        for (int i = 0; i < 8; i++) {
            int v = tid + i * 256;
            int r = v >> 5, w = v & 31;
            sm[OFF_RBFH + r * MPW + w] = rbfh[p0 * 32 + v];
            sm[OFF_RBFL + r * MPW + w] = rbfl[p0 * 32 + v];
        }
        __syncthreads();

        float acc[2][4][4];
        zero_acc(acc);
#pragma unroll
        for (int ks = 0; ks < 4; ks++) {
            const int kw = ks * 8 + tig;
            uint32_t ah[2][4], al[2][4];
#pragma unroll
            for (int mg = 0; mg < 2; mg++) {
                int ba = OFF_RBFH + (wr0 + mg * 16 + g) * MPW + kw;
                ah[mg][0] = sm[ba];            ah[mg][1] = sm[ba + 8 * MPW];
                ah[mg][2] = sm[ba + 4];        ah[mg][3] = sm[ba + 8 * MPW + 4];
                int bb2 = ba + (OFF_RBFL - OFF_RBFH);
                al[mg][0] = sm[bb2];            al[mg][1] = sm[bb2 + 8 * MPW];
                al[mg][2] = sm[bb2 + 4];        al[mg][3] = sm[bb2 + 8 * MPW + 4];
            }
#pragma unroll
            for (int ng = 0; ng < 4; ng++) {
                int nb = (wc0 + ng * 8 + g) * MPW + kw;
                uint32_t bh[2] = { sm[nb],        sm[nb + 4] };
                uint32_t bl[2] = { sm[nb + 4608], sm[nb + 4608 + 4] };
#pragma unroll
                for (int mg = 0; mg < 2; mg++) {
                    mma_bf16(acc[mg][ng], ah[mg], bh);
                    mma_bf16(acc[mg][ng], ah[mg], bl);
                    mma_bf16(acc[mg][ng], al[mg], bh);
                }
            }
        }

#pragma unroll
        for (int mg = 0; mg < 2; mg++) {
            int row = wr0 + mg * 16 + g;
#pragma unroll
            for (int ng = 0; ng < 4; ng++) {
                int col = wc0 + ng * 8 + 2 * tig;
                *(float2*)&gf[row * 132 + col]       = make_float2(acc[mg][ng][0], acc[mg][ng][1]);
                *(float2*)&gf[(row + 8) * 132 + col] = make_float2(acc[mg][ng][2], acc[mg][ng][3]);
            }
        }
        __syncthreads();

#pragma unroll
        for (int q = 0; q < 8; q++) {
            int r = wid * 8 + q, p = p0 + r;
            int i = idx_i[p], j = idx_j[p];
            float4 gv = *(const float4*)&gf[r * 132 + lane * 4];
            float4 xv = *(const float4*)(xj + (size_t)j * FDIM + lane * 4);
            red_add_f4(m + (size_t)i * FDIM + lane * 4,
                       make_float4(gv.x * xv.x, gv.y * xv.y, gv.z * xv.z, gv.w * xv.w));
        }
    }
}

__global__ void outblock_kernel(const float* __restrict__ o, const float* __restrict__ ow,
                                float* __restrict__ Ea, float* __restrict__ Qa,
                                float* __restrict__ last2, float* __restrict__ nh, int bpos) {
    int n = blockIdx.x, tid = threadIdx.x;
    float a = actf(o[n * FDIM + tid]);
    float e = a * ow[tid * 2], q = a * ow[tid * 2 + 1];
#pragma unroll
    for (int s = 16; s; s >>= 1) {
        e += __shfl_xor_sync(0xffffffffu, e, s);
        q += __shfl_xor_sync(0xffffffffu, q, s);
    }
    __shared__ float se[4], sq[4];
    if ((tid & 31) == 0) { se[tid >> 5] = e; sq[tid >> 5] = q; }
    __syncthreads();
    if (tid == 0) {
        e = se[0] + se[1] + se[2] + se[3];
        q = sq[0] + sq[1] + sq[2] + sq[3];
        Ea[n] += e; Qa[n] += q;
        float e2 = e * e, q2 = q * q;
        if (bpos) {
            float le = last2[2 * n], lq = last2[2 * n + 1];
            atomicAdd(nh, e2 / (e2 + le + 1e-7f) + q2 / (q2 + lq + 1e-7f));
        }
        last2[2 * n] = e2; last2[2 * n + 1] = q2;
    }
}

__global__ void final_kernel(const int* __restrict__ Z, const float* __restrict__ Ea,
                             const float* __restrict__ Qa, const float* __restrict__ nh,
                             const float* __restrict__ Es, const float* __restrict__ Eh,
                             const float* __restrict__ Qs, const float* __restrict__ Qh,
                             float* __restrict__ out) {
    int n = blockIdx.x * blockDim.x + threadIdx.x;
    if (n < NATOMS) {
        int z = Z[n];
        out[n]          = Es[z] * Ea[n] + Eh[z];
        out[NATOMS + n] = Qs[z] * Qa[n] + Qh[z];
    }
    if (n == 0) out[2 * NATOMS + NPAIRS] = *nh / (2.f * NATOMS);
}

// ---------------- launch ----------------
extern "C" void kernel_launch(void* const* d_in, const int* in_sizes, int n_in,
                              void* d_out, int out_size) {
    const int*   Z      = (const int*)  d_in[0];
    const float* R      = (const float*)d_in[1];
    const int*   idx_i  = (const int*)  d_in[2];
    const int*   idx_j  = (const int*)  d_in[3];
    const float* emb    = (const float*)d_in[4];
    const float* cent   = (const float*)d_in[5];
    const float* wid    = (const float*)d_in[6];
    const float* k2f    = (const float*)d_in[7];
    const float* Wi     = (const float*)d_in[8];
    const float* bi     = (const float*)d_in[9];
    const float* Wj     = (const float*)d_in[10];
    const float* bj     = (const float*)d_in[11];
    const float* riW1   = (const float*)d_in[12];
    const float* rib1   = (const float*)d_in[13];
    const float* riW2   = (const float*)d_in[14];
    const float* rib2   = (const float*)d_in[15];
    const float* dW     = (const float*)d_in[16];
    const float* db     = (const float*)d_in[17];
    const float* u      = (const float*)d_in[18];
    const float* raW1   = (const float*)d_in[19];
    const float* rab1   = (const float*)d_in[20];
    const float* raW2   = (const float*)d_in[21];
    const float* rab2   = (const float*)d_in[22];
    const float* roW1   = (const float*)d_in[23];
    const float* rob1   = (const float*)d_in[24];
    const float* roW2   = (const float*)d_in[25];
    const float* rob2   = (const float*)d_in[26];
    const float* outW   = (const float*)d_in[27];
    const float* Escale = (const float*)d_in[28];
    const float* Eshift = (const float*)d_in[29];
    const float* Qscale = (const float*)d_in[30];
    const float* Qshift = (const float*)d_in[31];
    float* out = (float*)d_out;

    float *x, *xjb, *m, *o, *Ea, *Qa, *l2, *nh;
    uint32_t *wbf, *rbfh, *rbfl, *k2fb;
    cudaGetSymbolAddress((void**)&rbfh, g_rbfh);
    cudaGetSymbolAddress((void**)&rbfl, g_rbfl);
    cudaGetSymbolAddress((void**)&k2fb, g_k2fb);
    cudaGetSymbolAddress((void**)&x,   g_x);
    cudaGetSymbolAddress((void**)&xjb, g_xj);
    cudaGetSymbolAddress((void**)&m,   g_m);
    cudaGetSymbolAddress((void**)&o,   g_o);
    cudaGetSymbolAddress((void**)&Ea,  g_Ea);
    cudaGetSymbolAddress((void**)&Qa,  g_Qa);
    cudaGetSymbolAddress((void**)&l2,  g_l2);
    cudaGetSymbolAddress((void**)&nh,  g_nh);
    cudaGetSymbolAddress((void**)&wbf, g_wbf);

    cudaFuncSetAttribute(gemm_dual_mma,  cudaFuncAttributeMaxDynamicSharedMemorySize, SM_DENSE);
    cudaFuncSetAttribute(gemm_resid_mma, cudaFuncAttributeMaxDynamicSharedMemorySize, SM_DENSE);
    cudaFuncSetAttribute(gemm_dw_mma,    cudaFuncAttributeMaxDynamicSharedMemorySize, SM_DENSE);
    cudaFuncSetAttribute(message_mma,    cudaFuncAttributeMaxDynamicSharedMemorySize, SM_MSG);

    cudaMemsetAsync(Ea, 0, NATOMS * sizeof(float));
    cudaMemsetAsync(Qa, 0, NATOMS * sizeof(float));
    cudaMemsetAsync(nh, 0, sizeof(float));

    // weight slots: Wi:0..4  Wj:5..9  riW1:10..24  riW2:25..39  dW:40..44
    // raW1:45..54  raW2:55..64  roW1:65..69  roW2:70..74
    WSrc ws;
    ws.p[0] = Wi;   ws.p[1] = Wj;   ws.p[2] = riW1; ws.p[3] = riW2; ws.p[4] = dW;
    ws.p[5] = raW1; ws.p[6] = raW2; ws.p[7] = roW1; ws.p[8] = roW2;
    conv_weights_all<<<(75 * 16384 + 255) / 256, 256>>>(ws, wbf);
    conv_k2f<<<(5 * 4096 + 255) / 256, 256>>>(k2f, k2fb);

    init_kernel<<<(NATOMS * FDIM + 255) / 256, 256>>>(Z, emb, x);
    pair_kernel<<<(NPAIRS * 32 + 255) / 256, 256>>>(R, idx_i, idx_j, cent, wid,
                                                    rbfh, rbfl, out + 2 * NATOMS);

    const int GB = (NATOMS + 63) / 64;  // 157
    auto WS = [&](int s) { return (const uint32_t*)(wbf + (size_t)s * MATW); };

    for (int b = 0; b < NB; b++) {
        gemm_dual_mma<<<GB, 256, SM_DENSE>>>(x, WS(0 + b), WS(5 + b),
                                             bi + b * 128, bj + b * 128, m, xjb, NATOMS);
        message_mma<<<296, 256, SM_MSG>>>(rbfh, rbfl, k2fb + (size_t)b * 9216,
                                          xjb, idx_i, idx_j, m);
        for (int l = 0; l < NRI; l++) {
            int wdx = b * NRI + l;
            gemm_resid_mma<<<GB, 256, SM_DENSE>>>(m, WS(10 + wdx), WS(25 + wdx),
                                                  rib1 + wdx * 128, rib2 + wdx * 128, m, NATOMS);
        }
        gemm_dw_mma<<<GB, 256, SM_DENSE>>>(m, WS(40 + b), db + b * 128, x, u + b * 128,
                                           x, NATOMS);
        for (int l = 0; l < NRA; l++) {
            int wdx = b * NRA + l;
            gemm_resid_mma<<<GB, 256, SM_DENSE>>>(x, WS(45 + wdx), WS(55 + wdx),
                                                  rab1 + wdx * 128, rab2 + wdx * 128, x, NATOMS);
        }
        gemm_resid_mma<<<GB, 256, SM_DENSE>>>(x, WS(65 + b), WS(70 + b),
                                              rob1 + b * 128, rob2 + b * 128, o, NATOMS);
        outblock_kernel<<<NATOMS, 128>>>(o, outW + b * FDIM * 2, Ea, Qa, l2, nh, b);
    }
    final_kernel<<<(NATOMS + 255) / 256, 256>>>(Z, Ea, Qa, nh, Escale, Eshift,
                                                Qscale, Qshift, out);
}

// round 14
// speedup vs baseline: 1.7971x; 1.1460x over previous
#include <cuda_runtime.h>
#include <cuda_bf16.h>
#include <cstdint>

#define NATOMS 10000
#define NPAIRS 320000
#define FDIM 128
#define KDIM 64
#define NB 5
#define NRI 3
#define NRA 2

// bf16 padded plane: 128 bf16/row = 64 words + 4 pad = 68 words
#define PW 68
#define A_LO 4352
#define WPLANE 8704          // one plane = 128 rows * 68 words
#define MATW 17408           // matrix = hi+lo planes
#define WS0 8704             // single W slot (hi at WS0, lo at WS0+WPLANE)
#define SM_DENSE (26112 * 4)     // dual: 104448B -> 2 CTAs/SM
#define SM_CHAIN ((26112 + 512) * 4)  // + 2KB reduction buffer -> still 2 CTAs/SM

// message MMA smem
#define MPW 36
#define OFF_RBFH 9216
#define OFF_RBFL 11520
#define OFF_G 13824
#define SM_MSG ((13824 + 8448) * 4)
#define NCH (NPAIRS / 64)

// ---------------- scratch ----------------
__device__ uint32_t g_rbfh[NPAIRS * 32];
__device__ uint32_t g_rbfl[NPAIRS * 32];
__device__ uint32_t g_k2fb[5 * 9216];
__device__ float g_x [NATOMS * FDIM];
__device__ float g_xj[NATOMS * FDIM];
__device__ float g_m [NATOMS * FDIM];
__device__ float g_Ea[NATOMS];
__device__ float g_Qa[NATOMS];
__device__ float g_l2[NATOMS * 2];
__device__ float g_nh;
__device__ uint32_t g_wbf[75 * MATW];

__device__ __forceinline__ float actf(float x) {
    return fmaxf(x, 0.f) + log1pf(__expf(-fabsf(x))) - 0.69314718055994531f;
}

__device__ __forceinline__ void red_add_f4(float* p, float4 v) {
    asm volatile("red.global.add.v4.f32 [%0], {%1,%2,%3,%4};"
                 :: "l"(p), "f"(v.x), "f"(v.y), "f"(v.z), "f"(v.w) : "memory");
}

__device__ __forceinline__ uint32_t pack_hi(float a, float b) {
    __nv_bfloat16 h0 = __float2bfloat16(a), h1 = __float2bfloat16(b);
    return (uint32_t)__bfloat16_as_ushort(h0) | ((uint32_t)__bfloat16_as_ushort(h1) << 16);
}
__device__ __forceinline__ uint32_t pack_lo(float a, float b) {
    __nv_bfloat16 h0 = __float2bfloat16(a), h1 = __float2bfloat16(b);
    float r0 = a - __bfloat162float(h0), r1 = b - __bfloat162float(h1);
    __nv_bfloat16 l0 = __float2bfloat16(r0), l1 = __float2bfloat16(r1);
    return (uint32_t)__bfloat16_as_ushort(l0) | ((uint32_t)__bfloat16_as_ushort(l1) << 16);
}

__device__ __forceinline__ void mma_bf16(float c[4], const uint32_t a[4], const uint32_t b[2]) {
    asm volatile(
        "mma.sync.aligned.m16n8k16.row.col.f32.bf16.bf16.f32 "
        "{%0,%1,%2,%3}, {%4,%5,%6,%7}, {%8,%9}, {%0,%1,%2,%3};"
        : "+f"(c[0]), "+f"(c[1]), "+f"(c[2]), "+f"(c[3])
        : "r"(a[0]), "r"(a[1]), "r"(a[2]), "r"(a[3]), "r"(b[0]), "r"(b[1]));
}

#define CP_COMMIT() asm volatile("cp.async.commit_group;" ::: "memory")
#define CP_WAIT0()  asm volatile("cp.async.wait_group 0;" ::: "memory")

// stream one full weight matrix (hi+lo planes = 4352 uint4) into the W slot
__device__ __forceinline__ void prefetch_mat(uint32_t* sm, const uint32_t* __restrict__ g,
                                             int tid) {
    uint32_t sb = (uint32_t)__cvta_generic_to_shared(sm + WS0);
#pragma unroll
    for (int i = 0; i < 17; i++) {
        int v = tid + i * 256;
        asm volatile("cp.async.cg.shared.global [%0], [%1], 16;"
                     :: "r"(sb + v * 16), "l"(g + v * 4) : "memory");
    }
    CP_COMMIT();
}

// ---- A tile from gmem: fp32 -> act -> bf16 hi/lo planes at offsets 0 / A_LO ----
__device__ __forceinline__ void conv_A(const float* __restrict__ A, uint32_t* sm,
                                       int tid, int r0, int nrows) {
#pragma unroll 4
    for (int i = 0; i < 16; i++) {
        int v = tid + i * 256;
        int row = v >> 6, kp = v & 63;
        float2 av = make_float2(0.f, 0.f);
        if (r0 + row < nrows) av = *(const float2*)(A + (size_t)(r0 + row) * FDIM + kp * 2);
        av.x = actf(av.x); av.y = actf(av.y);
        sm[row * PW + kp]        = pack_hi(av.x, av.y);
        sm[A_LO + row * PW + kp] = pack_lo(av.x, av.y);
    }
}

// ---- warp k-loop: acc += A @ W (bf16 hi/lo 3-combo), warp tile 32x32 ----
__device__ __forceinline__ void kloop(const uint32_t* __restrict__ sm, int woff,
                                      int wr0, int wc0, int lane, float acc[2][4][4]) {
    const int g = lane >> 2, tig = lane & 3;
#pragma unroll
    for (int ks = 0; ks < 8; ks++) {
        const int kw = ks * 8 + tig;
        uint32_t ah[2][4], al[2][4];
#pragma unroll
        for (int mg = 0; mg < 2; mg++) {
            int b = (wr0 + mg * 16 + g) * PW + kw;
            ah[mg][0] = sm[b];            ah[mg][1] = sm[b + 8 * PW];
            ah[mg][2] = sm[b + 4];        ah[mg][3] = sm[b + 8 * PW + 4];
            al[mg][0] = sm[A_LO + b];     al[mg][1] = sm[A_LO + b + 8 * PW];
            al[mg][2] = sm[A_LO + b + 4]; al[mg][3] = sm[A_LO + b + 8 * PW + 4];
        }
#pragma unroll
        for (int ng = 0; ng < 4; ng++) {
            int nb = woff + (wc0 + ng * 8 + g) * PW + kw;
            uint32_t bh[2] = { sm[nb],          sm[nb + 4] };
            uint32_t bl[2] = { sm[nb + WPLANE], sm[nb + WPLANE + 4] };
#pragma unroll
            for (int mg = 0; mg < 2; mg++) {
                mma_bf16(acc[mg][ng], ah[mg], bh);
                mma_bf16(acc[mg][ng], ah[mg], bl);
                mma_bf16(acc[mg][ng], al[mg], bh);
            }
        }
    }
}

__device__ __forceinline__ void zero_acc(float acc[2][4][4]) {
#pragma unroll
    for (int a = 0; a < 2; a++)
#pragma unroll
        for (int b = 0; b < 4; b++)
#pragma unroll
            for (int c = 0; c < 4; c++) acc[a][b][c] = 0.f;
}

// write h = act(acc + b1) into the A hi/lo planes (fragment positions)
__device__ __forceinline__ void write_h_planes(uint32_t* sm, const float acc[2][4][4],
                                               const float* __restrict__ b1,
                                               int wr0, int wc0, int g, int tig) {
#pragma unroll
    for (int mg = 0; mg < 2; mg++) {
        int ra = wr0 + mg * 16 + g, rb = ra + 8;
#pragma unroll
        for (int ng = 0; ng < 4; ng++) {
            int col = wc0 + ng * 8 + 2 * tig;
            float bv0 = b1[col], bv1 = b1[col + 1];
            float h0 = actf(acc[mg][ng][0] + bv0), h1 = actf(acc[mg][ng][1] + bv1);
            float h2 = actf(acc[mg][ng][2] + bv0), h3 = actf(acc[mg][ng][3] + bv1);
            int wa = ra * PW + (col >> 1), wb = rb * PW + (col >> 1);
            sm[wa] = pack_hi(h0, h1); sm[A_LO + wa] = pack_lo(h0, h1);
            sm[wb] = pack_hi(h2, h3); sm[A_LO + wb] = pack_lo(h2, h3);
        }
    }
}

// write act(frag) into the A hi/lo planes
__device__ __forceinline__ void write_act_planes(uint32_t* sm, const float f[2][4][4],
                                                 int wr0, int wc0, int g, int tig) {
#pragma unroll
    for (int mg = 0; mg < 2; mg++) {
        int ra = wr0 + mg * 16 + g, rb = ra + 8;
#pragma unroll
        for (int ng = 0; ng < 4; ng++) {
            int cw = (wc0 + ng * 8 + 2 * tig) >> 1;
            float a0 = actf(f[mg][ng][0]), a1 = actf(f[mg][ng][1]);
            float a2 = actf(f[mg][ng][2]), a3 = actf(f[mg][ng][3]);
            int wa = ra * PW + cw, wb = rb * PW + cw;
            sm[wa] = pack_hi(a0, a1); sm[A_LO + wa] = pack_lo(a0, a1);
            sm[wb] = pack_hi(a2, a3); sm[A_LO + wb] = pack_lo(a2, a3);
        }
    }
}

// stream-order matrix slot: i in 0..12
__device__ __forceinline__ int mat_slot(int i, int b) {
    if (i < 6)  return ((i & 1) ? 25 : 10) + 3 * b + (i >> 1);
    if (i == 6) return 40 + b;
    if (i < 11) return ((i - 7) & 1 ? 55 : 45) + 2 * b + ((i - 7) >> 1);
    return (i == 11 ? 65 : 70) + b;
}

// ---- dual: C1 = act(act(A)@W1+b1), C2 = act(act(A)@W2+b2); 2 CTAs/SM ----
__global__ void __launch_bounds__(256, 2) gemm_dual_mma(
    const float* __restrict__ A, const uint32_t* __restrict__ w1,
    const uint32_t* __restrict__ w2, const float* __restrict__ b1,
    const float* __restrict__ b2, float* __restrict__ C1, float* __restrict__ C2, int nrows) {
    extern __shared__ uint32_t sm[];
    const int tid = threadIdx.x, lane = tid & 31, wid = tid >> 5;
    const int wr0 = (wid >> 2) * 32, wc0 = (wid & 3) * 32;
    const int r0 = blockIdx.x * 64;
    const int g = lane >> 2, tig = lane & 3;

    prefetch_mat(sm, w1, tid);
    conv_A(A, sm, tid, r0, nrows);
    CP_WAIT0(); __syncthreads();

    float acc[2][4][4];
#pragma unroll
    for (int ph = 0; ph < 2; ph++) {
        zero_acc(acc);
        kloop(sm, WS0, wr0, wc0, lane, acc);
        __syncthreads();
        if (ph == 0) prefetch_mat(sm, w2, tid);
        const float* bb = ph ? b2 : b1;
        float* CC = ph ? C2 : C1;
#pragma unroll
        for (int mg = 0; mg < 2; mg++) {
            int ra = r0 + wr0 + mg * 16 + g, rb = ra + 8;
#pragma unroll
            for (int ng = 0; ng < 4; ng++) {
                int col = wc0 + ng * 8 + 2 * tig;
                float bv0 = bb[col], bv1 = bb[col + 1];
                if (ra < nrows)
                    *(float2*)(CC + (size_t)ra * FDIM + col) =
                        make_float2(actf(acc[mg][ng][0] + bv0), actf(acc[mg][ng][1] + bv1));
                if (rb < nrows)
                    *(float2*)(CC + (size_t)rb * FDIM + col) =
                        make_float2(actf(acc[mg][ng][2] + bv0), actf(acc[mg][ng][3] + bv1));
            }
        }
        if (ph == 0) { CP_WAIT0(); __syncthreads(); }
    }
}

// ---- chain: full post-message per-atom chain (13 matrices + outblock), 2 CTAs/SM ----
__global__ void __launch_bounds__(256, 2) chain_mma(
    const uint32_t* __restrict__ wbf, int b,
    const float* __restrict__ rib1, const float* __restrict__ rib2,
    const float* __restrict__ db, const float* __restrict__ uvec,
    const float* __restrict__ rab1, const float* __restrict__ rab2,
    const float* __restrict__ rob1, const float* __restrict__ rob2,
    const float* __restrict__ outW,
    const float* __restrict__ mbuf, float* __restrict__ xbuf,
    float* __restrict__ Ea, float* __restrict__ Qa,
    float* __restrict__ l2buf, float* __restrict__ nh, int nrows) {
    extern __shared__ uint32_t sm[];
    float* sred = (float*)(sm + 26112);   // [64][8] e/q partials
    const int tid = threadIdx.x, lane = tid & 31, wid = tid >> 5;
    const int wr0 = (wid >> 2) * 32, wc0 = (wid & 3) * 32;
    const int r0 = blockIdx.x * 64;
    const int g = lane >> 2, tig = lane & 3;

    prefetch_mat(sm, wbf + (size_t)mat_slot(0, b) * MATW, tid);
    conv_A(mbuf, sm, tid, r0, nrows);     // act(m) planes

    // residual fragment: holds m now, x after dw, stored per-thread
    float frag[2][4][4];
#pragma unroll
    for (int mg = 0; mg < 2; mg++) {
        int ra = r0 + wr0 + mg * 16 + g, rb = ra + 8;
#pragma unroll
        for (int ng = 0; ng < 4; ng++) {
            int col = wc0 + ng * 8 + 2 * tig;
            float2 v0 = make_float2(0.f, 0.f), v1 = v0;
            if (ra < nrows) v0 = *(const float2*)(mbuf + (size_t)ra * FDIM + col);
            if (rb < nrows) v1 = *(const float2*)(mbuf + (size_t)rb * FDIM + col);
            frag[mg][ng][0] = v0.x; frag[mg][ng][1] = v0.y;
            frag[mg][ng][2] = v1.x; frag[mg][ng][3] = v1.y;
        }
    }
    CP_WAIT0(); __syncthreads();

    float acc[2][4][4];
    int ni = 1;   // next matrix index in the 13-matrix stream

#pragma unroll 1
    for (int u = 0; u < 7; u++) {
        const float *b1p, *b2p;
        if (u < 3)      { b1p = rib1 + (3 * b + u) * 128;      b2p = rib2 + (3 * b + u) * 128; }
        else if (u == 3){ b1p = db + b * 128;                  b2p = uvec + b * 128; }
        else if (u < 6) { b1p = rab1 + (2 * b + u - 4) * 128;  b2p = rab2 + (2 * b + u - 4) * 128; }
        else            { b1p = rob1 + b * 128;                b2p = rob2 + b * 128; }

        zero_acc(acc);
        kloop(sm, WS0, wr0, wc0, lane, acc);
        __syncthreads();
        if (ni < 13) { prefetch_mat(sm, wbf + (size_t)mat_slot(ni, b) * MATW, tid); ni++; }

        if (u == 3) {
            // dw: frag(x) = uvec * x_gmem + acc + db ; planes = act(frag)
#pragma unroll
            for (int mg = 0; mg < 2; mg++) {
                int ra = r0 + wr0 + mg * 16 + g, rb = ra + 8;
#pragma unroll
                for (int ng = 0; ng < 4; ng++) {
                    int col = wc0 + ng * 8 + 2 * tig;
                    float bv0 = b1p[col], bv1 = b1p[col + 1];   // db
                    float u0 = b2p[col], u1 = b2p[col + 1];     // uvec
                    float2 x0 = make_float2(0.f, 0.f), x1 = x0;
                    if (ra < nrows) x0 = *(const float2*)(xbuf + (size_t)ra * FDIM + col);
                    if (rb < nrows) x1 = *(const float2*)(xbuf + (size_t)rb * FDIM + col);
                    frag[mg][ng][0] = u0 * x0.x + acc[mg][ng][0] + bv0;
                    frag[mg][ng][1] = u1 * x0.y + acc[mg][ng][1] + bv1;
                    frag[mg][ng][2] = u0 * x1.x + acc[mg][ng][2] + bv0;
                    frag[mg][ng][3] = u1 * x1.y + acc[mg][ng][3] + bv1;
                }
            }
            write_act_planes(sm, frag, wr0, wc0, g, tig);
            CP_WAIT0(); __syncthreads();
            continue;
        }

        // two-matrix residual unit: h planes, then second kloop
        write_h_planes(sm, acc, b1p, wr0, wc0, g, tig);
        CP_WAIT0(); __syncthreads();

        zero_acc(acc);
        kloop(sm, WS0, wr0, wc0, lane, acc);
        __syncthreads();
        if (ni < 13) { prefetch_mat(sm, wbf + (size_t)mat_slot(ni, b) * MATW, tid); ni++; }

        if (u == 6) {
            // o = frag(x) + acc + b2 -> keep in acc
#pragma unroll
            for (int mg = 0; mg < 2; mg++)
#pragma unroll
                for (int ng = 0; ng < 4; ng++) {
                    int col = wc0 + ng * 8 + 2 * tig;
                    float bv0 = b2p[col], bv1 = b2p[col + 1];
                    acc[mg][ng][0] += frag[mg][ng][0] + bv0;
                    acc[mg][ng][1] += frag[mg][ng][1] + bv1;
                    acc[mg][ng][2] += frag[mg][ng][2] + bv0;
                    acc[mg][ng][3] += frag[mg][ng][3] + bv1;
                }
            break;
        }

        // frag += acc + b2 ; planes = act(frag)
#pragma unroll
        for (int mg = 0; mg < 2; mg++)
#pragma unroll
            for (int ng = 0; ng < 4; ng++) {
                int col = wc0 + ng * 8 + 2 * tig;
                float bv0 = b2p[col], bv1 = b2p[col + 1];
                frag[mg][ng][0] += acc[mg][ng][0] + bv0;
                frag[mg][ng][1] += acc[mg][ng][1] + bv1;
                frag[mg][ng][2] += acc[mg][ng][2] + bv0;
                frag[mg][ng][3] += acc[mg][ng][3] + bv1;
            }
        write_act_planes(sm, frag, wr0, wc0, g, tig);
        if (u == 5) {   // last ra: store final x
#pragma unroll
            for (int mg = 0; mg < 2; mg++) {
                int ra = r0 + wr0 + mg * 16 + g, rb = ra + 8;
#pragma unroll
                for (int ng = 0; ng < 4; ng++) {
                    int col = wc0 + ng * 8 + 2 * tig;
                    if (ra < nrows)
                        *(float2*)(xbuf + (size_t)ra * FDIM + col) =
                            make_float2(frag[mg][ng][0], frag[mg][ng][1]);
                    if (rb < nrows)
                        *(float2*)(xbuf + (size_t)rb * FDIM + col) =
                            make_float2(frag[mg][ng][2], frag[mg][ng][3]);
                }
            }
        }
        CP_WAIT0(); __syncthreads();
    }

    // ---- outblock: out = act(o) @ outW[b] (128x2), o in acc ----
    const float* ow = outW + b * 256;
    float ep[4] = {0.f, 0.f, 0.f, 0.f}, qp[4] = {0.f, 0.f, 0.f, 0.f};
#pragma unroll
    for (int mg = 0; mg < 2; mg++)
#pragma unroll
        for (int ng = 0; ng < 4; ng++) {
            int col = wc0 + ng * 8 + 2 * tig;
            float o0 = actf(acc[mg][ng][0]), o1 = actf(acc[mg][ng][1]);
            float o2 = actf(acc[mg][ng][2]), o3 = actf(acc[mg][ng][3]);
            float e0 = ow[col * 2], q0 = ow[col * 2 + 1];
            float e1 = ow[col * 2 + 2], q1 = ow[col * 2 + 3];
            ep[2 * mg]     += o0 * e0 + o1 * e1;
            qp[2 * mg]     += o0 * q0 + o1 * q1;
            ep[2 * mg + 1] += o2 * e0 + o3 * e1;
            qp[2 * mg + 1] += o2 * q0 + o3 * q1;
        }
#pragma unroll
    for (int s = 1; s <= 2; s <<= 1)
#pragma unroll
        for (int i = 0; i < 4; i++) {
            ep[i] += __shfl_xor_sync(0xffffffffu, ep[i], s);
            qp[i] += __shfl_xor_sync(0xffffffffu, qp[i], s);
        }
    if (tig == 0) {
#pragma unroll
        for (int i = 0; i < 4; i++) {
            int row = wr0 + (i >> 1) * 16 + (i & 1) * 8 + g;
            sred[row * 8 + (wid & 3) * 2]     = ep[i];
            sred[row * 8 + (wid & 3) * 2 + 1] = qp[i];
        }
    }
    __syncthreads();
    if (wid == 0) {
        float nhsum = 0.f;
#pragma unroll
        for (int h = 0; h < 2; h++) {
            int row = lane + h * 32;
            float e = sred[row * 8] + sred[row * 8 + 2] + sred[row * 8 + 4] + sred[row * 8 + 6];
            float q = sred[row * 8 + 1] + sred[row * 8 + 3] + sred[row * 8 + 5] + sred[row * 8 + 7];
            int grow = r0 + row;
            if (grow < nrows) {
                Ea[grow] += e; Qa[grow] += q;
                float e2 = e * e, q2 = q * q;
                if (b > 0) {
                    float le = l2buf[2 * grow], lq = l2buf[2 * grow + 1];
                    nhsum += e2 / (e2 + le + 1e-7f) + q2 / (q2 + lq + 1e-7f);
                }
                l2buf[2 * grow] = e2; l2buf[2 * grow + 1] = q2;
            }
        }
#pragma unroll
        for (int s = 16; s; s >>= 1) nhsum += __shfl_xor_sync(0xffffffffu, nhsum, s);
        if (lane == 0 && nhsum != 0.f) atomicAdd(nh, nhsum);
    }
}

// ---- fused weight conversion ----
struct WSrc { const float* p[9]; };

__global__ void conv_weights_all(WSrc s, uint32_t* __restrict__ dst) {
    int gid = blockIdx.x * blockDim.x + threadIdx.x;
    if (gid >= 75 * 16384) return;
    int m = gid >> 14, e = gid & 16383;
    int grp, loc;
    if      (m < 5)  { grp = 0; loc = m; }
    else if (m < 10) { grp = 1; loc = m - 5; }
    else if (m < 25) { grp = 2; loc = m - 10; }
    else if (m < 40) { grp = 3; loc = m - 25; }
    else if (m < 45) { grp = 4; loc = m - 40; }
    else if (m < 55) { grp = 5; loc = m - 45; }
    else if (m < 65) { grp = 6; loc = m - 55; }
    else if (m < 70) { grp = 7; loc = m - 65; }
    else             { grp = 8; loc = m - 70; }
    float x = s.p[grp][loc * 16384 + e];
    int k = e >> 7, n = e & 127;
    __nv_bfloat16 hi = __float2bfloat16(x);
    __nv_bfloat16 lo = __float2bfloat16(x - __bfloat162float(hi));
    char* bp = (char*)(dst + (size_t)m * MATW);
    *(__nv_bfloat16*)(bp + n * 272 + k * 2)         = hi;
    *(__nv_bfloat16*)(bp + 34816 + n * 272 + k * 2) = lo;
}

__global__ void conv_k2f(const float* __restrict__ src, uint32_t* __restrict__ dst) {
    int gid = blockIdx.x * blockDim.x + threadIdx.x;
    if (gid >= 5 * 4096) return;
    int b = gid >> 12, r = gid & 4095;
    int n = r >> 5, w = r & 31;
    const float* s = src + b * 8192;
    float x0 = s[(2 * w) * 128 + n], x1 = s[(2 * w + 1) * 128 + n];
    dst[b * 9216 + n * MPW + w]        = pack_hi(x0, x1);
    dst[b * 9216 + 4608 + n * MPW + w] = pack_lo(x0, x1);
}

__global__ void init_kernel(const int* __restrict__ Z, const float* __restrict__ emb,
                            float* __restrict__ x) {
    int idx = blockIdx.x * blockDim.x + threadIdx.x;
    if (idx < NATOMS * FDIM) {
        int n = idx >> 7, f = idx & 127;
        x[idx] = emb[Z[n] * FDIM + f];
    }
}

__global__ void pair_kernel(const float* __restrict__ R, const int* __restrict__ idx_i,
                            const int* __restrict__ idx_j, const float* __restrict__ cent,
                            const float* __restrict__ wid,
                            uint32_t* __restrict__ rbfh, uint32_t* __restrict__ rbfl,
                            float* __restrict__ Dij_out) {
    int gid = blockIdx.x * blockDim.x + threadIdx.x;
    int p = gid >> 5, w = gid & 31;
    if (p >= NPAIRS) return;
    int i = idx_i[p], j = idx_j[p];
    float dx = R[i * 3 + 0] - R[j * 3 + 0];
    float dy = R[i * 3 + 1] - R[j * 3 + 1];
    float dz = R[i * 3 + 2] - R[j * 3 + 2];
    float D = sqrtf(fmaxf(dx * dx + dy * dy + dz * dz, 0.f));
    if (w == 0) Dij_out[p] = D;
    float xr = D * 0.1f;
    float cut = 0.f;
    if (xr < 1.f) {
        float x3 = xr * xr * xr, x4 = x3 * xr, x5 = x4 * xr;
        cut = 1.f - 6.f * x5 + 15.f * x4 - 10.f * x3;
    }
    float ed = __expf(-D);
    float t0 = ed - cent[2 * w], t1 = ed - cent[2 * w + 1];
    float r0 = cut * __expf(-wid[2 * w] * t0 * t0);
    float r1 = cut * __expf(-wid[2 * w + 1] * t1 * t1);
    rbfh[p * 32 + w] = pack_hi(r0, r1);
    rbfl[p * 32 + w] = pack_lo(r0, r1);
}

__global__ void __launch_bounds__(256, 2) message_mma(
    const uint32_t* __restrict__ rbfh, const uint32_t* __restrict__ rbfl,
    const uint32_t* __restrict__ k2f, const float* __restrict__ xj,
    const int* __restrict__ idx_i, const int* __restrict__ idx_j,
    float* __restrict__ m) {
    extern __shared__ uint32_t sm[];
    float* gf = (float*)(sm + OFF_G);
    const int tid = threadIdx.x, lane = tid & 31, wid = tid >> 5;
    const int g = lane >> 2, tig = lane & 3;
    const int wr0 = (wid >> 2) * 32, wc0 = (wid & 3) * 32;

    {
        const uint4* kv = (const uint4*)k2f;
        uint4* sv = (uint4*)sm;
#pragma unroll
        for (int i = 0; i < 9; i++) sv[tid + i * 256] = kv[tid + i * 256];
    }

    for (int ch = blockIdx.x; ch < NCH; ch += gridDim.x) {
        const int p0 = ch * 64;
        __syncthreads();
#pragma unroll
        for (int i = 0; i < 8; i++) {
            int v = tid + i * 256;
            int r = v >> 5, w = v & 31;
            sm[OFF_RBFH + r * MPW + w] = rbfh[p0 * 32 + v];
            sm[OFF_RBFL + r * MPW + w] = rbfl[p0 * 32 + v];
        }
        __syncthreads();

        float acc[2][4][4];
        zero_acc(acc);
#pragma unroll
        for (int ks = 0; ks < 4; ks++) {
            const int kw = ks * 8 + tig;
            uint32_t ah[2][4], al[2][4];
#pragma unroll
            for (int mg = 0; mg < 2; mg++) {
                int ba = OFF_RBFH + (wr0 + mg * 16 + g) * MPW + kw;
                ah[mg][0] = sm[ba];            ah[mg][1] = sm[ba + 8 * MPW];
                ah[mg][2] = sm[ba + 4];        ah[mg][3] = sm[ba + 8 * MPW + 4];
                int bb2 = ba + (OFF_RBFL - OFF_RBFH);
                al[mg][0] = sm[bb2];            al[mg][1] = sm[bb2 + 8 * MPW];
                al[mg][2] = sm[bb2 + 4];        al[mg][3] = sm[bb2 + 8 * MPW + 4];
            }
#pragma unroll
            for (int ng = 0; ng < 4; ng++) {
                int nb = (wc0 + ng * 8 + g) * MPW + kw;
                uint32_t bh[2] = { sm[nb],        sm[nb + 4] };
                uint32_t bl[2] = { sm[nb + 4608], sm[nb + 4608 + 4] };
#pragma unroll
                for (int mg = 0; mg < 2; mg++) {
                    mma_bf16(acc[mg][ng], ah[mg], bh);
                    mma_bf16(acc[mg][ng], ah[mg], bl);
                    mma_bf16(acc[mg][ng], al[mg], bh);
                }
            }
        }

#pragma unroll
        for (int mg = 0; mg < 2; mg++) {
            int row = wr0 + mg * 16 + g;
#pragma unroll
            for (int ng = 0; ng < 4; ng++) {
                int col = wc0 + ng * 8 + 2 * tig;
                *(float2*)&gf[row * 132 + col]       = make_float2(acc[mg][ng][0], acc[mg][ng][1]);
                *(float2*)&gf[(row + 8) * 132 + col] = make_float2(acc[mg][ng][2], acc[mg][ng][3]);
            }
        }
        __syncthreads();

#pragma unroll
        for (int q = 0; q < 8; q++) {
            int r = wid * 8 + q, p = p0 + r;
            int i = idx_i[p], j = idx_j[p];
            float4 gv = *(const float4*)&gf[r * 132 + lane * 4];
            float4 xv = *(const float4*)(xj + (size_t)j * FDIM + lane * 4);
            red_add_f4(m + (size_t)i * FDIM + lane * 4,
                       make_float4(gv.x * xv.x, gv.y * xv.y, gv.z * xv.z, gv.w * xv.w));
        }
    }
}

__global__ void final_kernel(const int* __restrict__ Z, const float* __restrict__ Ea,
                             const float* __restrict__ Qa, const float* __restrict__ nh,
                             const float* __restrict__ Es, const float* __restrict__ Eh,
                             const float* __restrict__ Qs, const float* __restrict__ Qh,
                             float* __restrict__ out) {
    int n = blockIdx.x * blockDim.x + threadIdx.x;
    if (n < NATOMS) {
        int z = Z[n];
        out[n]          = Es[z] * Ea[n] + Eh[z];
        out[NATOMS + n] = Qs[z] * Qa[n] + Qh[z];
    }
    if (n == 0) out[2 * NATOMS + NPAIRS] = *nh / (2.f * NATOMS);
}

// ---------------- launch ----------------
extern "C" void kernel_launch(void* const* d_in, const int* in_sizes, int n_in,
                              void* d_out, int out_size) {
    const int*   Z      = (const int*)  d_in[0];
    const float* R      = (const float*)d_in[1];
    const int*   idx_i  = (const int*)  d_in[2];
    const int*   idx_j  = (const int*)  d_in[3];
    const float* emb    = (const float*)d_in[4];
    const float* cent   = (const float*)d_in[5];
    const float* wid    = (const float*)d_in[6];
    const float* k2f    = (const float*)d_in[7];
    const float* Wi     = (const float*)d_in[8];
    const float* bi     = (const float*)d_in[9];
    const float* Wj     = (const float*)d_in[10];
    const float* bj     = (const float*)d_in[11];
    const float* riW1   = (const float*)d_in[12];
    const float* rib1   = (const float*)d_in[13];
    const float* riW2   = (const float*)d_in[14];
    const float* rib2   = (const float*)d_in[15];
    const float* dW     = (const float*)d_in[16];
    const float* db     = (const float*)d_in[17];
    const float* u      = (const float*)d_in[18];
    const float* raW1   = (const float*)d_in[19];
    const float* rab1   = (const float*)d_in[20];
    const float* raW2   = (const float*)d_in[21];
    const float* rab2   = (const float*)d_in[22];
    const float* roW1   = (const float*)d_in[23];
    const float* rob1   = (const float*)d_in[24];
    const float* roW2   = (const float*)d_in[25];
    const float* rob2   = (const float*)d_in[26];
    const float* outW   = (const float*)d_in[27];
    const float* Escale = (const float*)d_in[28];
    const float* Eshift = (const float*)d_in[29];
    const float* Qscale = (const float*)d_in[30];
    const float* Qshift = (const float*)d_in[31];
    float* out = (float*)d_out;

    float *x, *xjb, *m, *Ea, *Qa, *l2, *nh;
    uint32_t *wbf, *rbfh, *rbfl, *k2fb;
    cudaGetSymbolAddress((void**)&rbfh, g_rbfh);
    cudaGetSymbolAddress((void**)&rbfl, g_rbfl);
    cudaGetSymbolAddress((void**)&k2fb, g_k2fb);
    cudaGetSymbolAddress((void**)&x,   g_x);
    cudaGetSymbolAddress((void**)&xjb, g_xj);
    cudaGetSymbolAddress((void**)&m,   g_m);
    cudaGetSymbolAddress((void**)&Ea,  g_Ea);
    cudaGetSymbolAddress((void**)&Qa,  g_Qa);
    cudaGetSymbolAddress((void**)&l2,  g_l2);
    cudaGetSymbolAddress((void**)&nh,  g_nh);
    cudaGetSymbolAddress((void**)&wbf, g_wbf);

    cudaFuncSetAttribute(gemm_dual_mma, cudaFuncAttributeMaxDynamicSharedMemorySize, SM_DENSE);
    cudaFuncSetAttribute(chain_mma,     cudaFuncAttributeMaxDynamicSharedMemorySize, SM_CHAIN);
    cudaFuncSetAttribute(message_mma,   cudaFuncAttributeMaxDynamicSharedMemorySize, SM_MSG);

    cudaMemsetAsync(Ea, 0, NATOMS * sizeof(float));
    cudaMemsetAsync(Qa, 0, NATOMS * sizeof(float));
    cudaMemsetAsync(nh, 0, sizeof(float));

    WSrc ws;
    ws.p[0] = Wi;   ws.p[1] = Wj;   ws.p[2] = riW1; ws.p[3] = riW2; ws.p[4] = dW;
    ws.p[5] = raW1; ws.p[6] = raW2; ws.p[7] = roW1; ws.p[8] = roW2;
    conv_weights_all<<<(75 * 16384 + 255) / 256, 256>>>(ws, wbf);
    conv_k2f<<<(5 * 4096 + 255) / 256, 256>>>(k2f, k2fb);

    init_kernel<<<(NATOMS * FDIM + 255) / 256, 256>>>(Z, emb, x);
    pair_kernel<<<(NPAIRS * 32 + 255) / 256, 256>>>(R, idx_i, idx_j, cent, wid,
                                                    rbfh, rbfl, out + 2 * NATOMS);

    const int GB = (NATOMS + 63) / 64;  // 157
    for (int b = 0; b < NB; b++) {
        gemm_dual_mma<<<GB, 256, SM_DENSE>>>(x, wbf + (size_t)(0 + b) * MATW,
                                             wbf + (size_t)(5 + b) * MATW,
                                             bi + b * 128, bj + b * 128, m, xjb, NATOMS);
        message_mma<<<296, 256, SM_MSG>>>(rbfh, rbfl, k2fb + (size_t)b * 9216,
                                          xjb, idx_i, idx_j, m);
        chain_mma<<<GB, 256, SM_CHAIN>>>(wbf, b, rib1, rib2, db, u, rab1, rab2,
                                         rob1, rob2, outW, m, x, Ea, Qa, l2, nh, NATOMS);
    }
    final_kernel<<<(NATOMS + 255) / 256, 256>>>(Z, Ea, Qa, nh, Escale, Eshift,
                                                Qscale, Qshift, out);
}